// round 4
// baseline (speedup 1.0000x reference)
#include <cuda_runtime.h>
#include <cuda_bf16.h>
#include <cstdint>

#define MAXN 50000
#define MAXE 800000
#define MAXF 128

typedef unsigned long long u64;

// ---------------- device scratch (allocation-free) ----------------
__device__ int   g_cnt_src[MAXN];
__device__ int   g_cnt_dst[MAXN];
__device__ float g_norm_src[MAXN];
__device__ float g_norm_dst[MAXN];
__device__ int   g_rowptr[MAXN + 1];
__device__ int   g_cursor[MAXN];
__device__ int   g_esrc[MAXE];
__device__ float g_t[(size_t)MAXN * MAXF];
__device__ float g_h[(size_t)MAXN * MAXF];

// ---------------- f32x2 packed math helpers ----------------
__device__ __forceinline__ u64 dup2(float v) {
    u64 r; asm("mov.b64 %0, {%1, %1};" : "=l"(r) : "f"(v)); return r;
}
__device__ __forceinline__ void fma2(u64& d, u64 a, u64 b) {
    asm("fma.rn.f32x2 %0, %1, %2, %0;" : "+l"(d) : "l"(a), "l"(b));
}
__device__ __forceinline__ void unpack2(u64 v, float& lo, float& hi) {
    asm("mov.b64 {%0, %1}, %2;" : "=f"(lo), "=f"(hi) : "l"(v));
}

// ---------------- degree histograms (4 edges / thread, int4 loads) ----------------
__global__ void degree_kernel(const int* __restrict__ src, const int* __restrict__ dst, int E) {
    int e0 = (blockIdx.x * blockDim.x + threadIdx.x) * 4;
    if (e0 + 3 < E) {
        int4 s = *(const int4*)&src[e0];
        int4 d = *(const int4*)&dst[e0];
        atomicAdd(&g_cnt_src[s.x], 1); atomicAdd(&g_cnt_src[s.y], 1);
        atomicAdd(&g_cnt_src[s.z], 1); atomicAdd(&g_cnt_src[s.w], 1);
        atomicAdd(&g_cnt_dst[d.x], 1); atomicAdd(&g_cnt_dst[d.y], 1);
        atomicAdd(&g_cnt_dst[d.z], 1); atomicAdd(&g_cnt_dst[d.w], 1);
    } else {
        for (int e = e0; e < E; e++) {
            atomicAdd(&g_cnt_src[src[e]], 1);
            atomicAdd(&g_cnt_dst[dst[e]], 1);
        }
    }
}

// ------- fused scan (4 elems/thread) + norms + cursor init -------
__global__ void scan_kernel(int Nn) {
    __shared__ int wsum[32];
    __shared__ int s_carry;
    int lane = threadIdx.x & 31;
    int wid  = threadIdx.x >> 5;
    if (threadIdx.x == 0) { s_carry = 0; g_rowptr[0] = 0; }
    __syncthreads();
    for (int base = 0; base < Nn; base += 4096) {
        int i0 = base + (int)threadIdx.x * 4;
        int4 v  = make_int4(0, 0, 0, 0);
        int4 cs = make_int4(0, 0, 0, 0);
        if (i0 + 3 < Nn) {
            v  = *(const int4*)&g_cnt_dst[i0];
            cs = *(const int4*)&g_cnt_src[i0];
        } else if (i0 < Nn) {
            for (int k = 0; k < 4 && i0 + k < Nn; k++) {
                ((int*)&v)[k]  = g_cnt_dst[i0 + k];
                ((int*)&cs)[k] = g_cnt_src[i0 + k];
            }
        }
        int s = v.x + v.y + v.z + v.w;
        int xs = s;
        #pragma unroll
        for (int off = 1; off < 32; off <<= 1) {
            int y = __shfl_up_sync(0xffffffffu, xs, off);
            if (lane >= off) xs += y;
        }
        if (lane == 31) wsum[wid] = xs;
        __syncthreads();
        if (wid == 0) {
            int w = wsum[lane];
            #pragma unroll
            for (int off = 1; off < 32; off <<= 1) {
                int y = __shfl_up_sync(0xffffffffu, w, off);
                if (lane >= off) w += y;
            }
            wsum[lane] = w;
        }
        __syncthreads();
        int p = s_carry + (xs - s) + (wid ? wsum[wid - 1] : 0);
        #pragma unroll
        for (int k = 0; k < 4; k++) {
            int idx = i0 + k;
            if (idx < Nn) {
                int vk  = ((int*)&v)[k];
                int csk = ((int*)&cs)[k];
                g_cursor[idx] = p;
                p += vk;
                g_rowptr[idx + 1] = p;
                if (csk < 1) csk = 1;
                int cd = vk < 1 ? 1 : vk;
                g_norm_src[idx] = rsqrtf((float)csk);
                g_norm_dst[idx] = rsqrtf((float)cd);
            }
        }
        __syncthreads();
        if (threadIdx.x == 0) s_carry += wsum[31];
        __syncthreads();
    }
}

// ---------------- bin edges by destination (4 edges / thread) ----------------
__global__ void bin_kernel(const int* __restrict__ src, const int* __restrict__ dst, int E) {
    int e0 = (blockIdx.x * blockDim.x + threadIdx.x) * 4;
    if (e0 + 3 < E) {
        int4 s = *(const int4*)&src[e0];
        int4 d = *(const int4*)&dst[e0];
        int p0 = atomicAdd(&g_cursor[d.x], 1);
        int p1 = atomicAdd(&g_cursor[d.y], 1);
        int p2 = atomicAdd(&g_cursor[d.z], 1);
        int p3 = atomicAdd(&g_cursor[d.w], 1);
        g_esrc[p0] = s.x; g_esrc[p1] = s.y; g_esrc[p2] = s.z; g_esrc[p3] = s.w;
    } else {
        for (int e = e0; e < E; e++) {
            int p = atomicAdd(&g_cursor[dst[e]], 1);
            g_esrc[p] = src[e];
        }
    }
}

// ------- GEMM: Cout[n,:] = (A[n,:] @ W) * norm_src[n] -------
// f32x2 FFMA2 inner loop; B pre-duplicated into u64 SMEM in a permuted,
// conflict-free layout: column n lives at sB2[k][(n%TN)*TXC + n/TN].
template <int DIN, int DOUT>
__global__ void __launch_bounds__(256) gemm_kernel(const float* __restrict__ A,
                                                   const float* __restrict__ W,
                                                   float* __restrict__ Cout, int Nn) {
    constexpr int BN  = (DOUT < 128) ? DOUT : 128;
    constexpr int TN  = (BN >= 64) ? 8 : 4;
    constexpr int TXC = BN / TN;          // 16, 8, 8, 4
    constexpr int TYC = 256 / TXC;        // 16, 32, 32, 64
    constexpr int TM  = 8;
    constexpr int TP  = TM / 2;           // 4 M-pairs
    constexpr int BM  = TYC * TM;         // 128, 256, 256, 512
    constexpr int BK  = 16;

    __shared__ float sA[BK][BM + 4];
    __shared__ u64   sB2[BK][BN];

    int row0 = blockIdx.x * BM;
    int col0 = blockIdx.y * BN;
    int tx = threadIdx.x % TXC;
    int ty = threadIdx.x / TXC;

    u64 acc[TP][TN];
    #pragma unroll
    for (int p = 0; p < TP; p++)
        #pragma unroll
        for (int j = 0; j < TN; j++) acc[p][j] = 0ull;

    for (int k0 = 0; k0 < DIN; k0 += BK) {
        // A tile: float4 global loads, transposed scatter into sA
        #pragma unroll
        for (int idx = threadIdx.x; idx < BM * BK / 4; idx += 256) {
            int r  = idx / (BK / 4);
            int c4 = (idx % (BK / 4)) * 4;
            int gr = row0 + r;
            float4 v = make_float4(0.f, 0.f, 0.f, 0.f);
            if (gr < Nn) v = *(const float4*)&A[(size_t)gr * DIN + k0 + c4];
            sA[c4 + 0][r] = v.x; sA[c4 + 1][r] = v.y;
            sA[c4 + 2][r] = v.z; sA[c4 + 3][r] = v.w;
        }
        // B tile: float4 loads, duplicated u64 stores in permuted layout
        #pragma unroll
        for (int idx = threadIdx.x; idx < BK * BN / 4; idx += 256) {
            int r  = idx / (BN / 4);
            int c4 = (idx % (BN / 4)) * 4;
            float4 v = *(const float4*)&W[(k0 + r) * DOUT + col0 + c4];
            sB2[r][((c4 + 0) % TN) * TXC + (c4 + 0) / TN] = dup2(v.x);
            sB2[r][((c4 + 1) % TN) * TXC + (c4 + 1) / TN] = dup2(v.y);
            sB2[r][((c4 + 2) % TN) * TXC + (c4 + 2) / TN] = dup2(v.z);
            sB2[r][((c4 + 3) % TN) * TXC + (c4 + 3) / TN] = dup2(v.w);
        }
        __syncthreads();
        #pragma unroll
        for (int kk = 0; kk < BK; kk++) {
            u64 a2[TP];
            #pragma unroll
            for (int p = 0; p < TP; p++)
                a2[p] = *(const u64*)&sA[kk][ty * TM + 2 * p];
            u64 b2[TN];
            #pragma unroll
            for (int j = 0; j < TN; j++)
                b2[j] = sB2[kk][j * TXC + tx];      // lanes hit consecutive banks
            #pragma unroll
            for (int p = 0; p < TP; p++)
                #pragma unroll
                for (int j = 0; j < TN; j++)
                    fma2(acc[p][j], a2[p], b2[j]);
        }
        __syncthreads();
    }
    // epilogue: unpack, scale by norm_src, float4 stores
    #pragma unroll
    for (int p = 0; p < TP; p++) {
        float lo[TN], hi[TN];
        #pragma unroll
        for (int j = 0; j < TN; j++) unpack2(acc[p][j], lo[j], hi[j]);
        int gr = row0 + ty * TM + 2 * p;
        if (gr < Nn) {
            float ns = g_norm_src[gr];
            #pragma unroll
            for (int j4 = 0; j4 < TN; j4 += 4) {
                float4 o = make_float4(lo[j4] * ns, lo[j4 + 1] * ns,
                                       lo[j4 + 2] * ns, lo[j4 + 3] * ns);
                *(float4*)&Cout[(size_t)gr * DOUT + col0 + tx * TN + j4] = o;
            }
        }
        if (gr + 1 < Nn) {
            float ns = g_norm_src[gr + 1];
            #pragma unroll
            for (int j4 = 0; j4 < TN; j4 += 4) {
                float4 o = make_float4(hi[j4] * ns, hi[j4 + 1] * ns,
                                       hi[j4 + 2] * ns, hi[j4 + 3] * ns);
                *(float4*)&Cout[(size_t)(gr + 1) * DOUT + col0 + tx * TN + j4] = o;
            }
        }
    }
}

// ------- CSR gather + norm_dst + bias + relu, float4 per thread -------
template <int D>
__global__ void __launch_bounds__(256) gather_kernel(const float* __restrict__ t,
                                                     const float* __restrict__ bias,
                                                     float* __restrict__ out, int Nn) {
    constexpr int TX = D / 4;
    int n = blockIdx.x * blockDim.y + threadIdx.y;
    if (n >= Nn) return;
    int f = threadIdx.x;
    const float4* t4 = (const float4*)t;
    int beg = g_rowptr[n], end = g_rowptr[n + 1];
    float4 acc = make_float4(0.f, 0.f, 0.f, 0.f);
    int j = beg;
    for (; j + 4 <= end; j += 4) {
        int s0 = g_esrc[j], s1 = g_esrc[j + 1], s2 = g_esrc[j + 2], s3 = g_esrc[j + 3];
        float4 v0 = t4[s0 * TX + f];
        float4 v1 = t4[s1 * TX + f];
        float4 v2 = t4[s2 * TX + f];
        float4 v3 = t4[s3 * TX + f];
        acc.x += (v0.x + v1.x) + (v2.x + v3.x);
        acc.y += (v0.y + v1.y) + (v2.y + v3.y);
        acc.z += (v0.z + v1.z) + (v2.z + v3.z);
        acc.w += (v0.w + v1.w) + (v2.w + v3.w);
    }
    for (; j < end; j++) {
        float4 v = t4[g_esrc[j] * TX + f];
        acc.x += v.x; acc.y += v.y; acc.z += v.z; acc.w += v.w;
    }
    float nd = g_norm_dst[n];
    float4 bb = ((const float4*)bias)[f];
    float4 o;
    o.x = fmaxf(fmaf(acc.x, nd, bb.x), 0.f);
    o.y = fmaxf(fmaf(acc.y, nd, bb.y), 0.f);
    o.z = fmaxf(fmaf(acc.z, nd, bb.z), 0.f);
    o.w = fmaxf(fmaf(acc.w, nd, bb.w), 0.f);
    ((float4*)out)[(size_t)n * TX + f] = o;
}

// ---------------- launch ----------------
extern "C" void kernel_launch(void* const* d_in, const int* in_sizes, int n_in,
                              void* d_out, int out_size) {
    const float* x  = (const float*)d_in[0];
    const int*   ed = (const int*)d_in[1];
    const float* W1 = (const float*)d_in[2];   const float* b1 = (const float*)d_in[3];
    const float* W2 = (const float*)d_in[4];   const float* b2 = (const float*)d_in[5];
    const float* W3 = (const float*)d_in[6];   const float* b3 = (const float*)d_in[7];
    const float* W4 = (const float*)d_in[8];   const float* b4 = (const float*)d_in[9];
    const float* W5 = (const float*)d_in[10];  const float* b5 = (const float*)d_in[11];

    const int Nn = in_sizes[0] / 128;
    const int E  = in_sizes[1] / 2;
    const int* src = ed;
    const int* dst = ed + E;

    void *pcs = nullptr, *pcd = nullptr, *pt = nullptr, *ph = nullptr;
    cudaGetSymbolAddress(&pcs, g_cnt_src);
    cudaGetSymbolAddress(&pcd, g_cnt_dst);
    cudaGetSymbolAddress(&pt,  g_t);
    cudaGetSymbolAddress(&ph,  g_h);
    float* t = (float*)pt;
    float* h = (float*)ph;

    cudaMemsetAsync(pcs, 0, Nn * sizeof(int), 0);
    cudaMemsetAsync(pcd, 0, Nn * sizeof(int), 0);

    int eb4 = (E / 4 + 255) / 256 + 1;
    degree_kernel<<<eb4, 256>>>(src, dst, E);
    scan_kernel<<<1, 1024>>>(Nn);
    bin_kernel<<<eb4, 256>>>(src, dst, E);

    // Layer 1: 128 -> 128   (BM=128, BN=128)
    gemm_kernel<128, 128><<<dim3((Nn + 127) / 128, 1), 256>>>(x, W1, t, Nn);
    gather_kernel<128><<<(Nn + 7) / 8, dim3(32, 8)>>>(t, b1, h, Nn);
    // Layer 2: 128 -> 64    (BM=256)
    gemm_kernel<128, 64><<<dim3((Nn + 255) / 256, 1), 256>>>(h, W2, t, Nn);
    gather_kernel<64><<<(Nn + 15) / 16, dim3(16, 16)>>>(t, b2, h, Nn);
    // Layer 3: 64 -> 32     (BM=256)
    gemm_kernel<64, 32><<<dim3((Nn + 255) / 256, 1), 256>>>(h, W3, t, Nn);
    gather_kernel<32><<<(Nn + 31) / 32, dim3(8, 32)>>>(t, b3, h, Nn);
    // Layer 4: 32 -> 16     (BM=512)
    gemm_kernel<32, 16><<<dim3((Nn + 511) / 512, 1), 256>>>(h, W4, t, Nn);
    gather_kernel<16><<<(Nn + 63) / 64, dim3(4, 64)>>>(t, b4, h, Nn);
    // Layer 5: 16 -> 16     (BM=512)
    gemm_kernel<16, 16><<<dim3((Nn + 511) / 512, 1), 256>>>(h, W5, t, Nn);
    gather_kernel<16><<<(Nn + 63) / 64, dim3(4, 64)>>>(t, b5, (float*)d_out, Nn);
}

// round 5
// speedup vs baseline: 1.5908x; 1.5908x over previous
#include <cuda_runtime.h>
#include <cuda_bf16.h>
#include <cstdint>

#define MAXN 50000
#define MAXE 800000
#define MAXF 128

typedef unsigned long long u64;

// ---------------- device scratch (allocation-free) ----------------
__device__ int   g_cnt_src[MAXN];
__device__ int   g_cnt_dst[MAXN];
__device__ float g_norm_src[MAXN];
__device__ float g_norm_dst[MAXN];
__device__ int   g_rowptr[MAXN + 1];
__device__ int   g_cursor[MAXN];
__device__ int   g_esrc[MAXE];
__device__ float g_t[(size_t)MAXN * MAXF];
__device__ float g_h[(size_t)MAXN * MAXF];

// ---------------- f32x2 packed math helpers ----------------
__device__ __forceinline__ u64 dup2(float v) {
    u64 r; asm("mov.b64 %0, {%1, %1};" : "=l"(r) : "f"(v)); return r;
}
__device__ __forceinline__ void fma2(u64& d, u64 a, u64 b) {
    asm("fma.rn.f32x2 %0, %1, %2, %0;" : "+l"(d) : "l"(a), "l"(b));
}
__device__ __forceinline__ void unpack2(u64 v, float& lo, float& hi) {
    asm("mov.b64 {%0, %1}, %2;" : "=f"(lo), "=f"(hi) : "l"(v));
}

// ---------------- degree histograms (4 edges / thread, int4 loads) ----------------
__global__ void degree_kernel(const int* __restrict__ src, const int* __restrict__ dst, int E) {
    int e0 = (blockIdx.x * blockDim.x + threadIdx.x) * 4;
    if (e0 + 3 < E) {
        int4 s = *(const int4*)&src[e0];
        int4 d = *(const int4*)&dst[e0];
        atomicAdd(&g_cnt_src[s.x], 1); atomicAdd(&g_cnt_src[s.y], 1);
        atomicAdd(&g_cnt_src[s.z], 1); atomicAdd(&g_cnt_src[s.w], 1);
        atomicAdd(&g_cnt_dst[d.x], 1); atomicAdd(&g_cnt_dst[d.y], 1);
        atomicAdd(&g_cnt_dst[d.z], 1); atomicAdd(&g_cnt_dst[d.w], 1);
    } else {
        for (int e = e0; e < E; e++) {
            atomicAdd(&g_cnt_src[src[e]], 1);
            atomicAdd(&g_cnt_dst[dst[e]], 1);
        }
    }
}

// ------- fused scan (4 elems/thread) + norms + cursor init -------
__global__ void scan_kernel(int Nn) {
    __shared__ int wsum[32];
    __shared__ int s_carry;
    int lane = threadIdx.x & 31;
    int wid  = threadIdx.x >> 5;
    if (threadIdx.x == 0) { s_carry = 0; g_rowptr[0] = 0; }
    __syncthreads();
    for (int base = 0; base < Nn; base += 4096) {
        int i0 = base + (int)threadIdx.x * 4;
        int4 v  = make_int4(0, 0, 0, 0);
        int4 cs = make_int4(0, 0, 0, 0);
        if (i0 + 3 < Nn) {
            v  = *(const int4*)&g_cnt_dst[i0];
            cs = *(const int4*)&g_cnt_src[i0];
        } else if (i0 < Nn) {
            for (int k = 0; k < 4 && i0 + k < Nn; k++) {
                ((int*)&v)[k]  = g_cnt_dst[i0 + k];
                ((int*)&cs)[k] = g_cnt_src[i0 + k];
            }
        }
        int s = v.x + v.y + v.z + v.w;
        int xs = s;
        #pragma unroll
        for (int off = 1; off < 32; off <<= 1) {
            int y = __shfl_up_sync(0xffffffffu, xs, off);
            if (lane >= off) xs += y;
        }
        if (lane == 31) wsum[wid] = xs;
        __syncthreads();
        if (wid == 0) {
            int w = wsum[lane];
            #pragma unroll
            for (int off = 1; off < 32; off <<= 1) {
                int y = __shfl_up_sync(0xffffffffu, w, off);
                if (lane >= off) w += y;
            }
            wsum[lane] = w;
        }
        __syncthreads();
        int p = s_carry + (xs - s) + (wid ? wsum[wid - 1] : 0);
        #pragma unroll
        for (int k = 0; k < 4; k++) {
            int idx = i0 + k;
            if (idx < Nn) {
                int vk  = ((int*)&v)[k];
                int csk = ((int*)&cs)[k];
                g_cursor[idx] = p;
                p += vk;
                g_rowptr[idx + 1] = p;
                if (csk < 1) csk = 1;
                int cd = vk < 1 ? 1 : vk;
                g_norm_src[idx] = rsqrtf((float)csk);
                g_norm_dst[idx] = rsqrtf((float)cd);
            }
        }
        __syncthreads();
        if (threadIdx.x == 0) s_carry += wsum[31];
        __syncthreads();
    }
}

// ---------------- bin edges by destination (4 edges / thread) ----------------
__global__ void bin_kernel(const int* __restrict__ src, const int* __restrict__ dst, int E) {
    int e0 = (blockIdx.x * blockDim.x + threadIdx.x) * 4;
    if (e0 + 3 < E) {
        int4 s = *(const int4*)&src[e0];
        int4 d = *(const int4*)&dst[e0];
        int p0 = atomicAdd(&g_cursor[d.x], 1);
        int p1 = atomicAdd(&g_cursor[d.y], 1);
        int p2 = atomicAdd(&g_cursor[d.z], 1);
        int p3 = atomicAdd(&g_cursor[d.w], 1);
        g_esrc[p0] = s.x; g_esrc[p1] = s.y; g_esrc[p2] = s.z; g_esrc[p3] = s.w;
    } else {
        for (int e = e0; e < E; e++) {
            int p = atomicAdd(&g_cursor[dst[e]], 1);
            g_esrc[p] = src[e];
        }
    }
}

// ------- GEMM: Cout[n,:] = (A[n,:] @ W) * norm_src[n] -------
// R2 tile shape (BM=128, TN=4, acc=32 regs) + pre-duplicated permuted B
// (no dup2 in inner loop) + double-buffered SMEM (1 sync per k-iter).
template <int DIN, int DOUT>
__global__ void __launch_bounds__(256) gemm_kernel(const float* __restrict__ A,
                                                   const float* __restrict__ W,
                                                   float* __restrict__ Cout, int Nn) {
    constexpr int BM  = 128;
    constexpr int BN  = (DOUT < 64) ? DOUT : 64;
    constexpr int BK  = 16;
    constexpr int TN  = 4;
    constexpr int TXC = BN / TN;          // 16, 8, 4
    constexpr int TYC = 256 / TXC;        // 16, 32, 64
    constexpr int TM  = BM / TYC;         // 8, 4, 2
    constexpr int TP  = TM / 2;           // 4, 2, 1
    constexpr int NA  = BM * BK / 4 / 256;  // float4 A loads per thread (2)
    constexpr int NB  = (BK * BN / 4 + 255) / 256;  // float4 B loads per thread (1)
    constexpr int NITER = DIN / BK;

    __shared__ float sA[2][BK][BM + 4];
    __shared__ u64   sB2[2][BK][BN];

    int row0 = blockIdx.x * BM;
    int col0 = blockIdx.y * BN;
    int tx = threadIdx.x % TXC;
    int ty = threadIdx.x / TXC;

    u64 acc[TP][TN];
    #pragma unroll
    for (int p = 0; p < TP; p++)
        #pragma unroll
        for (int j = 0; j < TN; j++) acc[p][j] = 0ull;

    // ---- stage tile 0 ----
    float4 pa[NA];
    float4 pb[NB];
    #pragma unroll
    for (int u = 0; u < NA; u++) {
        int idx = threadIdx.x + u * 256;
        int r  = idx / (BK / 4);
        int c4 = (idx % (BK / 4)) * 4;
        int gr = row0 + r;
        pa[u] = make_float4(0.f, 0.f, 0.f, 0.f);
        if (gr < Nn) pa[u] = *(const float4*)&A[(size_t)gr * DIN + c4];
    }
    #pragma unroll
    for (int u = 0; u < NB; u++) {
        int idx = threadIdx.x + u * 256;
        if (idx < BK * BN / 4) {
            int r  = idx / (BN / 4);
            int c4 = (idx % (BN / 4)) * 4;
            pb[u] = *(const float4*)&W[r * DOUT + col0 + c4];
        }
    }
    #pragma unroll
    for (int u = 0; u < NA; u++) {
        int idx = threadIdx.x + u * 256;
        int r  = idx / (BK / 4);
        int c4 = (idx % (BK / 4)) * 4;
        sA[0][c4 + 0][r] = pa[u].x; sA[0][c4 + 1][r] = pa[u].y;
        sA[0][c4 + 2][r] = pa[u].z; sA[0][c4 + 3][r] = pa[u].w;
    }
    #pragma unroll
    for (int u = 0; u < NB; u++) {
        int idx = threadIdx.x + u * 256;
        if (idx < BK * BN / 4) {
            int r  = idx / (BN / 4);
            int c4 = (idx % (BN / 4)) * 4;
            sB2[0][r][((c4 + 0) % TN) * TXC + (c4 + 0) / TN] = dup2(pb[u].x);
            sB2[0][r][((c4 + 1) % TN) * TXC + (c4 + 1) / TN] = dup2(pb[u].y);
            sB2[0][r][((c4 + 2) % TN) * TXC + (c4 + 2) / TN] = dup2(pb[u].z);
            sB2[0][r][((c4 + 3) % TN) * TXC + (c4 + 3) / TN] = dup2(pb[u].w);
        }
    }
    __syncthreads();

    #pragma unroll
    for (int it = 0; it < NITER; it++) {
        int cur = it & 1, nxt = cur ^ 1;
        // prefetch next tile into registers (overlaps with compute below)
        if (it + 1 < NITER) {
            int k0 = (it + 1) * BK;
            #pragma unroll
            for (int u = 0; u < NA; u++) {
                int idx = threadIdx.x + u * 256;
                int r  = idx / (BK / 4);
                int c4 = (idx % (BK / 4)) * 4;
                int gr = row0 + r;
                pa[u] = make_float4(0.f, 0.f, 0.f, 0.f);
                if (gr < Nn) pa[u] = *(const float4*)&A[(size_t)gr * DIN + k0 + c4];
            }
            #pragma unroll
            for (int u = 0; u < NB; u++) {
                int idx = threadIdx.x + u * 256;
                if (idx < BK * BN / 4) {
                    int r  = idx / (BN / 4);
                    int c4 = (idx % (BN / 4)) * 4;
                    pb[u] = *(const float4*)&W[(k0 + r) * DOUT + col0 + c4];
                }
            }
        }
        // compute on current tile
        #pragma unroll
        for (int kk = 0; kk < BK; kk++) {
            u64 a2[TP];
            #pragma unroll
            for (int p = 0; p < TP; p++)
                a2[p] = *(const u64*)&sA[cur][kk][ty * TM + 2 * p];
            u64 b2[TN];
            #pragma unroll
            for (int j = 0; j < TN; j++)
                b2[j] = sB2[cur][kk][j * TXC + tx];
            #pragma unroll
            for (int p = 0; p < TP; p++)
                #pragma unroll
                for (int j = 0; j < TN; j++)
                    fma2(acc[p][j], a2[p], b2[j]);
        }
        // store prefetched tile
        if (it + 1 < NITER) {
            #pragma unroll
            for (int u = 0; u < NA; u++) {
                int idx = threadIdx.x + u * 256;
                int r  = idx / (BK / 4);
                int c4 = (idx % (BK / 4)) * 4;
                sA[nxt][c4 + 0][r] = pa[u].x; sA[nxt][c4 + 1][r] = pa[u].y;
                sA[nxt][c4 + 2][r] = pa[u].z; sA[nxt][c4 + 3][r] = pa[u].w;
            }
            #pragma unroll
            for (int u = 0; u < NB; u++) {
                int idx = threadIdx.x + u * 256;
                if (idx < BK * BN / 4) {
                    int r  = idx / (BN / 4);
                    int c4 = (idx % (BN / 4)) * 4;
                    sB2[nxt][r][((c4 + 0) % TN) * TXC + (c4 + 0) / TN] = dup2(pb[u].x);
                    sB2[nxt][r][((c4 + 1) % TN) * TXC + (c4 + 1) / TN] = dup2(pb[u].y);
                    sB2[nxt][r][((c4 + 2) % TN) * TXC + (c4 + 2) / TN] = dup2(pb[u].z);
                    sB2[nxt][r][((c4 + 3) % TN) * TXC + (c4 + 3) / TN] = dup2(pb[u].w);
                }
            }
            __syncthreads();
        }
    }

    // epilogue: unpack, scale by norm_src, float4 stores
    #pragma unroll
    for (int p = 0; p < TP; p++) {
        float lo[TN], hi[TN];
        #pragma unroll
        for (int j = 0; j < TN; j++) unpack2(acc[p][j], lo[j], hi[j]);
        int gr = row0 + ty * TM + 2 * p;
        if (gr < Nn) {
            float ns = g_norm_src[gr];
            float4 o = make_float4(lo[0] * ns, lo[1] * ns, lo[2] * ns, lo[3] * ns);
            *(float4*)&Cout[(size_t)gr * DOUT + col0 + tx * TN] = o;
        }
        if (gr + 1 < Nn) {
            float ns = g_norm_src[gr + 1];
            float4 o = make_float4(hi[0] * ns, hi[1] * ns, hi[2] * ns, hi[3] * ns);
            *(float4*)&Cout[(size_t)(gr + 1) * DOUT + col0 + tx * TN] = o;
        }
    }
}

// ------- CSR gather + norm_dst + bias + relu, float4 per thread -------
template <int D>
__global__ void __launch_bounds__(256) gather_kernel(const float* __restrict__ t,
                                                     const float* __restrict__ bias,
                                                     float* __restrict__ out, int Nn) {
    constexpr int TX = D / 4;
    int n = blockIdx.x * blockDim.y + threadIdx.y;
    if (n >= Nn) return;
    int f = threadIdx.x;
    const float4* t4 = (const float4*)t;
    int beg = g_rowptr[n], end = g_rowptr[n + 1];
    float4 acc = make_float4(0.f, 0.f, 0.f, 0.f);
    int j = beg;
    for (; j + 4 <= end; j += 4) {
        int s0 = g_esrc[j], s1 = g_esrc[j + 1], s2 = g_esrc[j + 2], s3 = g_esrc[j + 3];
        float4 v0 = t4[s0 * TX + f];
        float4 v1 = t4[s1 * TX + f];
        float4 v2 = t4[s2 * TX + f];
        float4 v3 = t4[s3 * TX + f];
        acc.x += (v0.x + v1.x) + (v2.x + v3.x);
        acc.y += (v0.y + v1.y) + (v2.y + v3.y);
        acc.z += (v0.z + v1.z) + (v2.z + v3.z);
        acc.w += (v0.w + v1.w) + (v2.w + v3.w);
    }
    for (; j < end; j++) {
        float4 v = t4[g_esrc[j] * TX + f];
        acc.x += v.x; acc.y += v.y; acc.z += v.z; acc.w += v.w;
    }
    float nd = g_norm_dst[n];
    float4 bb = ((const float4*)bias)[f];
    float4 o;
    o.x = fmaxf(fmaf(acc.x, nd, bb.x), 0.f);
    o.y = fmaxf(fmaf(acc.y, nd, bb.y), 0.f);
    o.z = fmaxf(fmaf(acc.z, nd, bb.z), 0.f);
    o.w = fmaxf(fmaf(acc.w, nd, bb.w), 0.f);
    ((float4*)out)[(size_t)n * TX + f] = o;
}

// ---------------- launch ----------------
extern "C" void kernel_launch(void* const* d_in, const int* in_sizes, int n_in,
                              void* d_out, int out_size) {
    const float* x  = (const float*)d_in[0];
    const int*   ed = (const int*)d_in[1];
    const float* W1 = (const float*)d_in[2];   const float* b1 = (const float*)d_in[3];
    const float* W2 = (const float*)d_in[4];   const float* b2 = (const float*)d_in[5];
    const float* W3 = (const float*)d_in[6];   const float* b3 = (const float*)d_in[7];
    const float* W4 = (const float*)d_in[8];   const float* b4 = (const float*)d_in[9];
    const float* W5 = (const float*)d_in[10];  const float* b5 = (const float*)d_in[11];

    const int Nn = in_sizes[0] / 128;
    const int E  = in_sizes[1] / 2;
    const int* src = ed;
    const int* dst = ed + E;

    void *pcs = nullptr, *pcd = nullptr, *pt = nullptr, *ph = nullptr;
    cudaGetSymbolAddress(&pcs, g_cnt_src);
    cudaGetSymbolAddress(&pcd, g_cnt_dst);
    cudaGetSymbolAddress(&pt,  g_t);
    cudaGetSymbolAddress(&ph,  g_h);
    float* t = (float*)pt;
    float* h = (float*)ph;

    cudaMemsetAsync(pcs, 0, Nn * sizeof(int), 0);
    cudaMemsetAsync(pcd, 0, Nn * sizeof(int), 0);

    int eb4 = (E / 4 + 255) / 256 + 1;
    degree_kernel<<<eb4, 256>>>(src, dst, E);
    scan_kernel<<<1, 1024>>>(Nn);
    bin_kernel<<<eb4, 256>>>(src, dst, E);

    // Layer 1: 128 -> 128   (BM=128, BN=64, grid.y=2  — R2 shape)
    gemm_kernel<128, 128><<<dim3((Nn + 127) / 128, 2), 256>>>(x, W1, t, Nn);
    gather_kernel<128><<<(Nn + 7) / 8, dim3(32, 8)>>>(t, b1, h, Nn);
    // Layer 2: 128 -> 64
    gemm_kernel<128, 64><<<dim3((Nn + 127) / 128, 1), 256>>>(h, W2, t, Nn);
    gather_kernel<64><<<(Nn + 15) / 16, dim3(16, 16)>>>(t, b2, h, Nn);
    // Layer 3: 64 -> 32
    gemm_kernel<64, 32><<<dim3((Nn + 127) / 128, 1), 256>>>(h, W3, t, Nn);
    gather_kernel<32><<<(Nn + 31) / 32, dim3(8, 32)>>>(t, b3, h, Nn);
    // Layer 4: 32 -> 16
    gemm_kernel<32, 16><<<dim3((Nn + 127) / 128, 1), 256>>>(h, W4, t, Nn);
    gather_kernel<16><<<(Nn + 63) / 64, dim3(4, 64)>>>(t, b4, h, Nn);
    // Layer 5: 16 -> 16
    gemm_kernel<16, 16><<<dim3((Nn + 127) / 128, 1), 256>>>(h, W5, t, Nn);
    gather_kernel<16><<<(Nn + 63) / 64, dim3(4, 64)>>>(t, b5, (float*)d_out, Nn);
}

// round 7
// speedup vs baseline: 1.7571x; 1.1045x over previous
#include <cuda_runtime.h>
#include <cuda_fp16.h>
#include <cstdint>

#define MAXN 50000
#define MAXE 800000
#define MAXF 128

typedef unsigned long long u64;

// ---------------- device scratch (allocation-free) ----------------
__device__ int    g_cnt_src[MAXN];
__device__ int    g_cnt_dst[MAXN];
__device__ float  g_norm_src[MAXN];
__device__ float  g_norm_dst[MAXN];
__device__ int    g_rowptr[MAXN + 1];
__device__ int    g_cursor[MAXN];
__device__ int    g_esrc[MAXE];
__device__ __half g_t[(size_t)MAXN * MAXF];   // fp16 transformed features
__device__ float  g_h[(size_t)MAXN * MAXF];   // fp32 layer activations

// ---------------- f32x2 packed math helpers ----------------
__device__ __forceinline__ u64 dup2(float v) {
    u64 r; asm("mov.b64 %0, {%1, %1};" : "=l"(r) : "f"(v)); return r;
}
__device__ __forceinline__ void fma2(u64& d, u64 a, u64 b) {
    asm("fma.rn.f32x2 %0, %1, %2, %0;" : "+l"(d) : "l"(a), "l"(b));
}
__device__ __forceinline__ void unpack2(u64 v, float& lo, float& hi) {
    asm("mov.b64 {%0, %1}, %2;" : "=f"(lo), "=f"(hi) : "l"(v));
}

// ---------------- degree histograms (4 edges / thread, int4 loads) ----------------
__global__ void degree_kernel(const int* __restrict__ src, const int* __restrict__ dst, int E) {
    int e0 = (blockIdx.x * blockDim.x + threadIdx.x) * 4;
    if (e0 + 3 < E) {
        int4 s = *(const int4*)&src[e0];
        int4 d = *(const int4*)&dst[e0];
        atomicAdd(&g_cnt_src[s.x], 1); atomicAdd(&g_cnt_src[s.y], 1);
        atomicAdd(&g_cnt_src[s.z], 1); atomicAdd(&g_cnt_src[s.w], 1);
        atomicAdd(&g_cnt_dst[d.x], 1); atomicAdd(&g_cnt_dst[d.y], 1);
        atomicAdd(&g_cnt_dst[d.z], 1); atomicAdd(&g_cnt_dst[d.w], 1);
    } else {
        for (int e = e0; e < E; e++) {
            atomicAdd(&g_cnt_src[src[e]], 1);
            atomicAdd(&g_cnt_dst[dst[e]], 1);
        }
    }
}

// ------- fused scan (4 elems/thread) + norms + cursor init -------
__global__ void scan_kernel(int Nn) {
    __shared__ int wsum[32];
    __shared__ int s_carry;
    int lane = threadIdx.x & 31;
    int wid  = threadIdx.x >> 5;
    if (threadIdx.x == 0) { s_carry = 0; g_rowptr[0] = 0; }
    __syncthreads();
    for (int base = 0; base < Nn; base += 4096) {
        int i0 = base + (int)threadIdx.x * 4;
        int4 v  = make_int4(0, 0, 0, 0);
        int4 cs = make_int4(0, 0, 0, 0);
        if (i0 + 3 < Nn) {
            v  = *(const int4*)&g_cnt_dst[i0];
            cs = *(const int4*)&g_cnt_src[i0];
        } else if (i0 < Nn) {
            for (int k = 0; k < 4 && i0 + k < Nn; k++) {
                ((int*)&v)[k]  = g_cnt_dst[i0 + k];
                ((int*)&cs)[k] = g_cnt_src[i0 + k];
            }
        }
        int s = v.x + v.y + v.z + v.w;
        int xs = s;
        #pragma unroll
        for (int off = 1; off < 32; off <<= 1) {
            int y = __shfl_up_sync(0xffffffffu, xs, off);
            if (lane >= off) xs += y;
        }
        if (lane == 31) wsum[wid] = xs;
        __syncthreads();
        if (wid == 0) {
            int w = wsum[lane];
            #pragma unroll
            for (int off = 1; off < 32; off <<= 1) {
                int y = __shfl_up_sync(0xffffffffu, w, off);
                if (lane >= off) w += y;
            }
            wsum[lane] = w;
        }
        __syncthreads();
        int p = s_carry + (xs - s) + (wid ? wsum[wid - 1] : 0);
        #pragma unroll
        for (int k = 0; k < 4; k++) {
            int idx = i0 + k;
            if (idx < Nn) {
                int vk  = ((int*)&v)[k];
                int csk = ((int*)&cs)[k];
                g_cursor[idx] = p;
                p += vk;
                g_rowptr[idx + 1] = p;
                if (csk < 1) csk = 1;
                int cd = vk < 1 ? 1 : vk;
                g_norm_src[idx] = rsqrtf((float)csk);
                g_norm_dst[idx] = rsqrtf((float)cd);
            }
        }
        __syncthreads();
        if (threadIdx.x == 0) s_carry += wsum[31];
        __syncthreads();
    }
}

// ---------------- bin edges by destination (4 edges / thread) ----------------
__global__ void bin_kernel(const int* __restrict__ src, const int* __restrict__ dst, int E) {
    int e0 = (blockIdx.x * blockDim.x + threadIdx.x) * 4;
    if (e0 + 3 < E) {
        int4 s = *(const int4*)&src[e0];
        int4 d = *(const int4*)&dst[e0];
        int p0 = atomicAdd(&g_cursor[d.x], 1);
        int p1 = atomicAdd(&g_cursor[d.y], 1);
        int p2 = atomicAdd(&g_cursor[d.z], 1);
        int p3 = atomicAdd(&g_cursor[d.w], 1);
        g_esrc[p0] = s.x; g_esrc[p1] = s.y; g_esrc[p2] = s.z; g_esrc[p3] = s.w;
    } else {
        for (int e = e0; e < E; e++) {
            int p = atomicAdd(&g_cursor[dst[e]], 1);
            g_esrc[p] = src[e];
        }
    }
}

// ------- GEMM (R2 version): Cout[n,:] = half( (A[n,:] @ W) * norm_src[n] ) -------
template <int DIN, int DOUT>
__global__ void __launch_bounds__(256) gemm_kernel(const float* __restrict__ A,
                                                   const float* __restrict__ W,
                                                   __half* __restrict__ Cout, int Nn) {
    constexpr int BM = 128;
    constexpr int BN = (DOUT < 64) ? DOUT : 64;
    constexpr int BK = 16;
    constexpr int TN = 4;
    constexpr int TXC = BN / TN;          // 16, 8, 4
    constexpr int TYC = 256 / TXC;        // 16, 32, 64
    constexpr int TM = BM / TYC;          // 8, 4, 2
    constexpr int TP = TM / 2;            // M-pairs

    __shared__ float sA[BK][BM + 4];      // transposed, 16B-aligned row stride
    __shared__ float sB[BK][BN];

    int row0 = blockIdx.x * BM;
    int col0 = blockIdx.y * BN;
    int tx = threadIdx.x % TXC;
    int ty = threadIdx.x / TXC;

    u64 acc[TP][TN];
    #pragma unroll
    for (int p = 0; p < TP; p++)
        #pragma unroll
        for (int j = 0; j < TN; j++) acc[p][j] = 0ull;

    for (int k0 = 0; k0 < DIN; k0 += BK) {
        #pragma unroll
        for (int idx = threadIdx.x; idx < BM * BK / 4; idx += 256) {
            int r = idx / (BK / 4);
            int c4 = (idx % (BK / 4)) * 4;
            int gr = row0 + r;
            float4 v = make_float4(0.f, 0.f, 0.f, 0.f);
            if (gr < Nn) v = *(const float4*)&A[(size_t)gr * DIN + k0 + c4];
            sA[c4 + 0][r] = v.x; sA[c4 + 1][r] = v.y;
            sA[c4 + 2][r] = v.z; sA[c4 + 3][r] = v.w;
        }
        #pragma unroll
        for (int idx = threadIdx.x; idx < BK * BN / 4; idx += 256) {
            int r = idx / (BN / 4);
            int c4 = (idx % (BN / 4)) * 4;
            *(float4*)&sB[r][c4] = *(const float4*)&W[(k0 + r) * DOUT + col0 + c4];
        }
        __syncthreads();
        #pragma unroll
        for (int kk = 0; kk < BK; kk++) {
            u64 a2[TP];
            #pragma unroll
            for (int p = 0; p < TP; p++)
                a2[p] = *(const u64*)&sA[kk][ty * TM + 2 * p];
            u64 b2[TN];
            #pragma unroll
            for (int j = 0; j < TN; j++)
                b2[j] = dup2(sB[kk][tx * TN + j]);
            #pragma unroll
            for (int p = 0; p < TP; p++)
                #pragma unroll
                for (int j = 0; j < TN; j++)
                    fma2(acc[p][j], a2[p], b2[j]);
        }
        __syncthreads();
    }
    // epilogue: unpack pairs, scale by norm_src, fp16 stores (8B per row-chunk)
    #pragma unroll
    for (int p = 0; p < TP; p++) {
        float lo[TN], hi[TN];
        #pragma unroll
        for (int j = 0; j < TN; j++) unpack2(acc[p][j], lo[j], hi[j]);
        int gr = row0 + ty * TM + 2 * p;
        if (gr < Nn) {
            float ns = g_norm_src[gr];
            __half2 h0 = __floats2half2_rn(lo[0] * ns, lo[1] * ns);
            __half2 h1 = __floats2half2_rn(lo[2] * ns, lo[3] * ns);
            uint2 o; o.x = *(unsigned*)&h0; o.y = *(unsigned*)&h1;
            *(uint2*)&Cout[(size_t)gr * DOUT + col0 + tx * TN] = o;
        }
        if (gr + 1 < Nn) {
            float ns = g_norm_src[gr + 1];
            __half2 h0 = __floats2half2_rn(hi[0] * ns, hi[1] * ns);
            __half2 h1 = __floats2half2_rn(hi[2] * ns, hi[3] * ns);
            uint2 o; o.x = *(unsigned*)&h0; o.y = *(unsigned*)&h1;
            *(uint2*)&Cout[(size_t)(gr + 1) * DOUT + col0 + tx * TN] = o;
        }
    }
}

// ------- CSR gather (fp16 source) + norm_dst + bias + relu, fp32 accumulate -------
template <int D, bool LAST>
__global__ void __launch_bounds__(256) gather_kernel(const __half* __restrict__ t,
                                                     const float* __restrict__ bias,
                                                     float* __restrict__ out, int Nn) {
    constexpr int TX = D / 4;             // 8B lanes per node: 32,16,8,4
    int n = blockIdx.x * blockDim.y + threadIdx.y;
    if (n >= Nn) return;
    int f = threadIdx.x;
    const uint2* t4 = (const uint2*)t;    // 4 halfs per uint2
    int beg = g_rowptr[n], end = g_rowptr[n + 1];
    float4 acc = make_float4(0.f, 0.f, 0.f, 0.f);
    int j = beg;
    for (; j + 4 <= end; j += 4) {
        int s0 = g_esrc[j], s1 = g_esrc[j + 1], s2 = g_esrc[j + 2], s3 = g_esrc[j + 3];
        uint2 r0 = t4[s0 * TX + f];
        uint2 r1 = t4[s1 * TX + f];
        uint2 r2 = t4[s2 * TX + f];
        uint2 r3 = t4[s3 * TX + f];
        // pairwise half2 adds keep exact (half values are exact summands in fp32)
        float2 a0 = __half22float2(*(__half2*)&r0.x), b0 = __half22float2(*(__half2*)&r0.y);
        float2 a1 = __half22float2(*(__half2*)&r1.x), b1 = __half22float2(*(__half2*)&r1.y);
        float2 a2 = __half22float2(*(__half2*)&r2.x), b2 = __half22float2(*(__half2*)&r2.y);
        float2 a3 = __half22float2(*(__half2*)&r3.x), b3 = __half22float2(*(__half2*)&r3.y);
        acc.x += (a0.x + a1.x) + (a2.x + a3.x);
        acc.y += (a0.y + a1.y) + (a2.y + a3.y);
        acc.z += (b0.x + b1.x) + (b2.x + b3.x);
        acc.w += (b0.y + b1.y) + (b2.y + b3.y);
    }
    for (; j < end; j++) {
        uint2 r = t4[g_esrc[j] * TX + f];
        float2 a = __half22float2(*(__half2*)&r.x), b = __half22float2(*(__half2*)&r.y);
        acc.x += a.x; acc.y += a.y; acc.z += b.x; acc.w += b.y;
    }
    float nd = g_norm_dst[n];
    float4 bb = ((const float4*)bias)[f];
    float4 o;
    o.x = fmaxf(fmaf(acc.x, nd, bb.x), 0.f);
    o.y = fmaxf(fmaf(acc.y, nd, bb.y), 0.f);
    o.z = fmaxf(fmaf(acc.z, nd, bb.z), 0.f);
    o.w = fmaxf(fmaf(acc.w, nd, bb.w), 0.f);
    ((float4*)out)[(size_t)n * TX + f] = o;
}

// ---------------- launch ----------------
extern "C" void kernel_launch(void* const* d_in, const int* in_sizes, int n_in,
                              void* d_out, int out_size) {
    const float* x  = (const float*)d_in[0];
    const int*   ed = (const int*)d_in[1];
    const float* W1 = (const float*)d_in[2];   const float* b1 = (const float*)d_in[3];
    const float* W2 = (const float*)d_in[4];   const float* b2 = (const float*)d_in[5];
    const float* W3 = (const float*)d_in[6];   const float* b3 = (const float*)d_in[7];
    const float* W4 = (const float*)d_in[8];   const float* b4 = (const float*)d_in[9];
    const float* W5 = (const float*)d_in[10];  const float* b5 = (const float*)d_in[11];

    const int Nn = in_sizes[0] / 128;
    const int E  = in_sizes[1] / 2;
    const int* src = ed;
    const int* dst = ed + E;

    void *pcs = nullptr, *pcd = nullptr, *pt = nullptr, *ph = nullptr;
    cudaGetSymbolAddress(&pcs, g_cnt_src);
    cudaGetSymbolAddress(&pcd, g_cnt_dst);
    cudaGetSymbolAddress(&pt,  g_t);
    cudaGetSymbolAddress(&ph,  g_h);
    __half* t = (__half*)pt;
    float*  h = (float*)ph;

    cudaMemsetAsync(pcs, 0, Nn * sizeof(int), 0);
    cudaMemsetAsync(pcd, 0, Nn * sizeof(int), 0);

    int eb4 = (E / 4 + 255) / 256 + 1;
    degree_kernel<<<eb4, 256>>>(src, dst, E);
    scan_kernel<<<1, 1024>>>(Nn);
    bin_kernel<<<eb4, 256>>>(src, dst, E);

    // Layer 1: 128 -> 128
    gemm_kernel<128, 128><<<dim3((Nn + 127) / 128, 2), 256>>>(x, W1, t, Nn);
    gather_kernel<128, false><<<(Nn + 7) / 8, dim3(32, 8)>>>(t, b1, h, Nn);
    // Layer 2: 128 -> 64
    gemm_kernel<128, 64><<<dim3((Nn + 127) / 128, 1), 256>>>(h, W2, t, Nn);
    gather_kernel<64, false><<<(Nn + 15) / 16, dim3(16, 16)>>>(t, b2, h, Nn);
    // Layer 3: 64 -> 32
    gemm_kernel<64, 32><<<dim3((Nn + 127) / 128, 1), 256>>>(h, W3, t, Nn);
    gather_kernel<32, false><<<(Nn + 31) / 32, dim3(8, 32)>>>(t, b3, h, Nn);
    // Layer 4: 32 -> 16
    gemm_kernel<32, 16><<<dim3((Nn + 127) / 128, 1), 256>>>(h, W4, t, Nn);
    gather_kernel<16, false><<<(Nn + 63) / 64, dim3(4, 64)>>>(t, b4, h, Nn);
    // Layer 5: 16 -> 16
    gemm_kernel<16, 16><<<dim3((Nn + 127) / 128, 1), 256>>>(h, W5, t, Nn);
    gather_kernel<16, true><<<(Nn + 63) / 64, dim3(4, 64)>>>(t, b5, (float*)d_out, Nn);
}

// round 12
// speedup vs baseline: 1.9266x; 1.0965x over previous
#include <cuda_runtime.h>
#include <cuda_fp16.h>
#include <cstdint>

#define MAXN 50000
#define MAXE 800000
#define MAXF 128

typedef unsigned long long u64;

// ---------------- device scratch (allocation-free) ----------------
__device__ int    g_cnt_src[MAXN];
__device__ int    g_cnt_dst[MAXN];
__device__ float  g_norm_src[MAXN];
__device__ float  g_norm_dst[MAXN];
__device__ int    g_rowptr[MAXN + 1];
__device__ int    g_cursor[MAXN];
__device__ int    g_esrc[MAXE];
__device__ __half g_t[(size_t)MAXN * MAXF];   // fp16 transformed features
__device__ float  g_h[(size_t)MAXN * MAXF];   // fp32 layer activations

// ---------------- f32x2 packed math helpers ----------------
__device__ __forceinline__ u64 dup2(float v) {
    u64 r; asm("mov.b64 %0, {%1, %1};" : "=l"(r) : "f"(v)); return r;
}
__device__ __forceinline__ void fma2(u64& d, u64 a, u64 b) {
    asm("fma.rn.f32x2 %0, %1, %2, %0;" : "+l"(d) : "l"(a), "l"(b));
}
__device__ __forceinline__ void unpack2(u64 v, float& lo, float& hi) {
    asm("mov.b64 {%0, %1}, %2;" : "=f"(lo), "=f"(hi) : "l"(v));
}

// ---------------- hmma helper: m16n8k16 row.col f32 = f16*f16 + f32 ----------------
__device__ __forceinline__ void mma16816(float* c, const unsigned* a, unsigned b0, unsigned b1) {
    asm volatile(
        "mma.sync.aligned.m16n8k16.row.col.f32.f16.f16.f32 "
        "{%0,%1,%2,%3}, {%4,%5,%6,%7}, {%8,%9}, {%0,%1,%2,%3};"
        : "+f"(c[0]), "+f"(c[1]), "+f"(c[2]), "+f"(c[3])
        : "r"(a[0]), "r"(a[1]), "r"(a[2]), "r"(a[3]), "r"(b0), "r"(b1));
}

// ---------------- degree histograms (4 edges / thread, int4 loads) ----------------
__global__ void degree_kernel(const int* __restrict__ src, const int* __restrict__ dst, int E) {
    int e0 = (blockIdx.x * blockDim.x + threadIdx.x) * 4;
    if (e0 + 3 < E) {
        int4 s = *(const int4*)&src[e0];
        int4 d = *(const int4*)&dst[e0];
        atomicAdd(&g_cnt_src[s.x], 1); atomicAdd(&g_cnt_src[s.y], 1);
        atomicAdd(&g_cnt_src[s.z], 1); atomicAdd(&g_cnt_src[s.w], 1);
        atomicAdd(&g_cnt_dst[d.x], 1); atomicAdd(&g_cnt_dst[d.y], 1);
        atomicAdd(&g_cnt_dst[d.z], 1); atomicAdd(&g_cnt_dst[d.w], 1);
    } else {
        for (int e = e0; e < E; e++) {
            atomicAdd(&g_cnt_src[src[e]], 1);
            atomicAdd(&g_cnt_dst[dst[e]], 1);
        }
    }
}

// ------- fused scan (4 elems/thread) + norms + cursor init -------
__global__ void scan_kernel(int Nn) {
    __shared__ int wsum[32];
    __shared__ int s_carry;
    int lane = threadIdx.x & 31;
    int wid  = threadIdx.x >> 5;
    if (threadIdx.x == 0) { s_carry = 0; g_rowptr[0] = 0; }
    __syncthreads();
    for (int base = 0; base < Nn; base += 4096) {
        int i0 = base + (int)threadIdx.x * 4;
        int4 v  = make_int4(0, 0, 0, 0);
        int4 cs = make_int4(0, 0, 0, 0);
        if (i0 + 3 < Nn) {
            v  = *(const int4*)&g_cnt_dst[i0];
            cs = *(const int4*)&g_cnt_src[i0];
        } else if (i0 < Nn) {
            for (int k = 0; k < 4 && i0 + k < Nn; k++) {
                ((int*)&v)[k]  = g_cnt_dst[i0 + k];
                ((int*)&cs)[k] = g_cnt_src[i0 + k];
            }
        }
        int s = v.x + v.y + v.z + v.w;
        int xs = s;
        #pragma unroll
        for (int off = 1; off < 32; off <<= 1) {
            int y = __shfl_up_sync(0xffffffffu, xs, off);
            if (lane >= off) xs += y;
        }
        if (lane == 31) wsum[wid] = xs;
        __syncthreads();
        if (wid == 0) {
            int w = wsum[lane];
            #pragma unroll
            for (int off = 1; off < 32; off <<= 1) {
                int y = __shfl_up_sync(0xffffffffu, w, off);
                if (lane >= off) w += y;
            }
            wsum[lane] = w;
        }
        __syncthreads();
        int p = s_carry + (xs - s) + (wid ? wsum[wid - 1] : 0);
        #pragma unroll
        for (int k = 0; k < 4; k++) {
            int idx = i0 + k;
            if (idx < Nn) {
                int vk  = ((int*)&v)[k];
                int csk = ((int*)&cs)[k];
                g_cursor[idx] = p;
                p += vk;
                g_rowptr[idx + 1] = p;
                if (csk < 1) csk = 1;
                int cd = vk < 1 ? 1 : vk;
                g_norm_src[idx] = rsqrtf((float)csk);
                g_norm_dst[idx] = rsqrtf((float)cd);
            }
        }
        __syncthreads();
        if (threadIdx.x == 0) s_carry += wsum[31];
        __syncthreads();
    }
}

// ---------------- bin edges by destination (4 edges / thread) ----------------
__global__ void bin_kernel(const int* __restrict__ src, const int* __restrict__ dst, int E) {
    int e0 = (blockIdx.x * blockDim.x + threadIdx.x) * 4;
    if (e0 + 3 < E) {
        int4 s = *(const int4*)&src[e0];
        int4 d = *(const int4*)&dst[e0];
        int p0 = atomicAdd(&g_cursor[d.x], 1);
        int p1 = atomicAdd(&g_cursor[d.y], 1);
        int p2 = atomicAdd(&g_cursor[d.z], 1);
        int p3 = atomicAdd(&g_cursor[d.w], 1);
        g_esrc[p0] = s.x; g_esrc[p1] = s.y; g_esrc[p2] = s.z; g_esrc[p3] = s.w;
    } else {
        for (int e = e0; e < E; e++) {
            int p = atomicAdd(&g_cursor[dst[e]], 1);
            g_esrc[p] = src[e];
        }
    }
}

// ------- HMMA GEMM (layers 1-2): Cout[n,:] = half( (A[n,:] @ W) * norm_src[n] ) -------
// CTA: 8 warps, M-tile = 128 nodes, full N = DOUT, full K = DIN in SMEM.
// Warp grid 4(M) x 2(N): each warp 32 x DOUT/2 via m16n8k16 tiles.
template <int DIN, int DOUT>
__global__ void __launch_bounds__(256) gemm_mma_kernel(const float* __restrict__ A,
                                                       const float* __restrict__ W,
                                                       __half* __restrict__ Cout, int Nn) {
    constexpr int SAK   = DIN + 8;          // padded stride (halfs); word stride 68 -> conflict-free
    constexpr int WN    = DOUT / 2;         // N per warp (64 or 32)
    constexpr int NT_N  = WN / 8;           // n-tiles per warp (8 or 4)
    constexpr int KSTEP = DIN / 16;

    extern __shared__ __half sm[];
    __half* sA = sm;                        // [128][SAK]
    __half* sB = sm + 128 * SAK;            // [DOUT][SAK]  (B = W^T: sB[n][k])

    int tid  = threadIdx.x;
    int row0 = blockIdx.x * 128;

    // stage A: fp32 -> fp16, row-major padded
    for (int idx = tid; idx < 128 * DIN / 4; idx += 256) {
        int r  = idx / (DIN / 4);
        int c4 = (idx % (DIN / 4)) * 4;
        int gr = row0 + r;
        float4 v = make_float4(0.f, 0.f, 0.f, 0.f);
        if (gr < Nn) v = *(const float4*)&A[(size_t)gr * DIN + c4];
        __half2 h0 = __floats2half2_rn(v.x, v.y);
        __half2 h1 = __floats2half2_rn(v.z, v.w);
        uint2 pk; pk.x = *(unsigned*)&h0; pk.y = *(unsigned*)&h1;
        *(uint2*)&sA[r * SAK + c4] = pk;
    }
    // stage B = W^T (scalar fp16 stores, scattered — small tile, one-time cost)
    for (int idx = tid; idx < DIN * DOUT / 4; idx += 256) {
        int k  = idx / (DOUT / 4);
        int n4 = (idx % (DOUT / 4)) * 4;
        float4 v = *(const float4*)&W[(size_t)k * DOUT + n4];
        sB[(n4 + 0) * SAK + k] = __float2half(v.x);
        sB[(n4 + 1) * SAK + k] = __float2half(v.y);
        sB[(n4 + 2) * SAK + k] = __float2half(v.z);
        sB[(n4 + 3) * SAK + k] = __float2half(v.w);
    }
    __syncthreads();

    int wid  = tid >> 5;
    int lane = tid & 31;
    int grp  = lane >> 2;                   // 0..7
    int tig  = lane & 3;                    // 0..3
    int wm   = wid & 3;                     // M warp index (0..3)
    int wn   = wid >> 2;                    // N warp index (0..1)
    int m_base = wm * 32;
    int n_base = wn * WN;

    float acc[2][NT_N][4];
    #pragma unroll
    for (int mt = 0; mt < 2; mt++)
        #pragma unroll
        for (int nt = 0; nt < NT_N; nt++)
            #pragma unroll
            for (int q = 0; q < 4; q++) acc[mt][nt][q] = 0.f;

    #pragma unroll
    for (int ks = 0; ks < KSTEP; ks++) {
        int k0 = ks * 16 + tig * 2;
        unsigned a[2][4];
        #pragma unroll
        for (int mt = 0; mt < 2; mt++) {
            int g = m_base + mt * 16 + grp;
            a[mt][0] = *(const unsigned*)&sA[g * SAK + k0];
            a[mt][1] = *(const unsigned*)&sA[(g + 8) * SAK + k0];
            a[mt][2] = *(const unsigned*)&sA[g * SAK + k0 + 8];
            a[mt][3] = *(const unsigned*)&sA[(g + 8) * SAK + k0 + 8];
        }
        #pragma unroll
        for (int nt = 0; nt < NT_N; nt++) {
            int n = n_base + nt * 8 + grp;
            unsigned b0 = *(const unsigned*)&sB[n * SAK + k0];
            unsigned b1 = *(const unsigned*)&sB[n * SAK + k0 + 8];
            mma16816(acc[0][nt], a[0], b0, b1);
            mma16816(acc[1][nt], a[1], b0, b1);
        }
    }

    // epilogue: scale by norm_src, half2 stores from C fragments
    #pragma unroll
    for (int mt = 0; mt < 2; mt++) {
        int g0 = row0 + m_base + mt * 16 + grp;
        int g1 = g0 + 8;
        float ns0 = (g0 < Nn) ? g_norm_src[g0] : 0.f;
        float ns1 = (g1 < Nn) ? g_norm_src[g1] : 0.f;
        #pragma unroll
        for (int nt = 0; nt < NT_N; nt++) {
            int col = n_base + nt * 8 + tig * 2;
            if (g0 < Nn) {
                __half2 h = __floats2half2_rn(acc[mt][nt][0] * ns0, acc[mt][nt][1] * ns0);
                *(__half2*)&Cout[(size_t)g0 * DOUT + col] = h;
            }
            if (g1 < Nn) {
                __half2 h = __floats2half2_rn(acc[mt][nt][2] * ns1, acc[mt][nt][3] * ns1);
                *(__half2*)&Cout[(size_t)g1 * DOUT + col] = h;
            }
        }
    }
}

// ------- f32x2 SIMT GEMM (layers 3-5): Cout = half((A @ W) * norm_src) -------
template <int DIN, int DOUT>
__global__ void __launch_bounds__(256) gemm_kernel(const float* __restrict__ A,
                                                   const float* __restrict__ W,
                                                   __half* __restrict__ Cout, int Nn) {
    constexpr int BM = 128;
    constexpr int BN = (DOUT < 64) ? DOUT : 64;
    constexpr int BK = 16;
    constexpr int TN = 4;
    constexpr int TXC = BN / TN;
    constexpr int TYC = 256 / TXC;
    constexpr int TM = BM / TYC;
    constexpr int TP = TM / 2;

    __shared__ float sA[BK][BM + 4];
    __shared__ float sB[BK][BN];

    int row0 = blockIdx.x * BM;
    int col0 = blockIdx.y * BN;
    int tx = threadIdx.x % TXC;
    int ty = threadIdx.x / TXC;

    u64 acc[TP][TN];
    #pragma unroll
    for (int p = 0; p < TP; p++)
        #pragma unroll
        for (int j = 0; j < TN; j++) acc[p][j] = 0ull;

    for (int k0 = 0; k0 < DIN; k0 += BK) {
        #pragma unroll
        for (int idx = threadIdx.x; idx < BM * BK / 4; idx += 256) {
            int r = idx / (BK / 4);
            int c4 = (idx % (BK / 4)) * 4;
            int gr = row0 + r;
            float4 v = make_float4(0.f, 0.f, 0.f, 0.f);
            if (gr < Nn) v = *(const float4*)&A[(size_t)gr * DIN + k0 + c4];
            sA[c4 + 0][r] = v.x; sA[c4 + 1][r] = v.y;
            sA[c4 + 2][r] = v.z; sA[c4 + 3][r] = v.w;
        }
        #pragma unroll
        for (int idx = threadIdx.x; idx < BK * BN / 4; idx += 256) {
            int r = idx / (BN / 4);
            int c4 = (idx % (BN / 4)) * 4;
            *(float4*)&sB[r][c4] = *(const float4*)&W[(k0 + r) * DOUT + col0 + c4];
        }
        __syncthreads();
        #pragma unroll
        for (int kk = 0; kk < BK; kk++) {
            u64 a2[TP];
            #pragma unroll
            for (int p = 0; p < TP; p++)
                a2[p] = *(const u64*)&sA[kk][ty * TM + 2 * p];
            u64 b2[TN];
            #pragma unroll
            for (int j = 0; j < TN; j++)
                b2[j] = dup2(sB[kk][tx * TN + j]);
            #pragma unroll
            for (int p = 0; p < TP; p++)
                #pragma unroll
                for (int j = 0; j < TN; j++)
                    fma2(acc[p][j], a2[p], b2[j]);
        }
        __syncthreads();
    }
    #pragma unroll
    for (int p = 0; p < TP; p++) {
        float lo[TN], hi[TN];
        #pragma unroll
        for (int j = 0; j < TN; j++) unpack2(acc[p][j], lo[j], hi[j]);
        int gr = row0 + ty * TM + 2 * p;
        if (gr < Nn) {
            float ns = g_norm_src[gr];
            __half2 h0 = __floats2half2_rn(lo[0] * ns, lo[1] * ns);
            __half2 h1 = __floats2half2_rn(lo[2] * ns, lo[3] * ns);
            uint2 o; o.x = *(unsigned*)&h0; o.y = *(unsigned*)&h1;
            *(uint2*)&Cout[(size_t)gr * DOUT + col0 + tx * TN] = o;
        }
        if (gr + 1 < Nn) {
            float ns = g_norm_src[gr + 1];
            __half2 h0 = __floats2half2_rn(hi[0] * ns, hi[1] * ns);
            __half2 h1 = __floats2half2_rn(hi[2] * ns, hi[3] * ns);
            uint2 o; o.x = *(unsigned*)&h0; o.y = *(unsigned*)&h1;
            *(uint2*)&Cout[(size_t)(gr + 1) * DOUT + col0 + tx * TN] = o;
        }
    }
}

// ------- CSR gather (fp16 source) + norm_dst + bias + relu, fp32 accumulate -------
template <int D, bool LAST>
__global__ void __launch_bounds__(256) gather_kernel(const __half* __restrict__ t,
                                                     const float* __restrict__ bias,
                                                     float* __restrict__ out, int Nn) {
    constexpr int TX = D / 4;
    int n = blockIdx.x * blockDim.y + threadIdx.y;
    if (n >= Nn) return;
    int f = threadIdx.x;
    const uint2* t4 = (const uint2*)t;
    int beg = g_rowptr[n], end = g_rowptr[n + 1];
    float4 acc = make_float4(0.f, 0.f, 0.f, 0.f);
    int j = beg;
    for (; j + 4 <= end; j += 4) {
        int s0 = g_esrc[j], s1 = g_esrc[j + 1], s2 = g_esrc[j + 2], s3 = g_esrc[j + 3];
        uint2 r0 = t4[s0 * TX + f];
        uint2 r1 = t4[s1 * TX + f];
        uint2 r2 = t4[s2 * TX + f];
        uint2 r3 = t4[s3 * TX + f];
        float2 a0 = __half22float2(*(__half2*)&r0.x), b0 = __half22float2(*(__half2*)&r0.y);
        float2 a1 = __half22float2(*(__half2*)&r1.x), b1 = __half22float2(*(__half2*)&r1.y);
        float2 a2 = __half22float2(*(__half2*)&r2.x), b2 = __half22float2(*(__half2*)&r2.y);
        float2 a3 = __half22float2(*(__half2*)&r3.x), b3 = __half22float2(*(__half2*)&r3.y);
        acc.x += (a0.x + a1.x) + (a2.x + a3.x);
        acc.y += (a0.y + a1.y) + (a2.y + a3.y);
        acc.z += (b0.x + b1.x) + (b2.x + b3.x);
        acc.w += (b0.y + b1.y) + (b2.y + b3.y);
    }
    for (; j < end; j++) {
        uint2 r = t4[g_esrc[j] * TX + f];
        float2 a = __half22float2(*(__half2*)&r.x), b = __half22float2(*(__half2*)&r.y);
        acc.x += a.x; acc.y += a.y; acc.z += b.x; acc.w += b.y;
    }
    float nd = g_norm_dst[n];
    float4 bb = ((const float4*)bias)[f];
    float4 o;
    o.x = fmaxf(fmaf(acc.x, nd, bb.x), 0.f);
    o.y = fmaxf(fmaf(acc.y, nd, bb.y), 0.f);
    o.z = fmaxf(fmaf(acc.z, nd, bb.z), 0.f);
    o.w = fmaxf(fmaf(acc.w, nd, bb.w), 0.f);
    ((float4*)out)[(size_t)n * TX + f] = o;
}

// ---------------- launch ----------------
extern "C" void kernel_launch(void* const* d_in, const int* in_sizes, int n_in,
                              void* d_out, int out_size) {
    const float* x  = (const float*)d_in[0];
    const int*   ed = (const int*)d_in[1];
    const float* W1 = (const float*)d_in[2];   const float* b1 = (const float*)d_in[3];
    const float* W2 = (const float*)d_in[4];   const float* b2 = (const float*)d_in[5];
    const float* W3 = (const float*)d_in[6];   const float* b3 = (const float*)d_in[7];
    const float* W4 = (const float*)d_in[8];   const float* b4 = (const float*)d_in[9];
    const float* W5 = (const float*)d_in[10];  const float* b5 = (const float*)d_in[11];

    const int Nn = in_sizes[0] / 128;
    const int E  = in_sizes[1] / 2;
    const int* src = ed;
    const int* dst = ed + E;

    void *pcs = nullptr, *pcd = nullptr, *pt = nullptr, *ph = nullptr;
    cudaGetSymbolAddress(&pcs, g_cnt_src);
    cudaGetSymbolAddress(&pcd, g_cnt_dst);
    cudaGetSymbolAddress(&pt,  g_t);
    cudaGetSymbolAddress(&ph,  g_h);
    __half* t = (__half*)pt;
    float*  h = (float*)ph;

    cudaMemsetAsync(pcs, 0, Nn * sizeof(int), 0);
    cudaMemsetAsync(pcd, 0, Nn * sizeof(int), 0);

    int eb4 = (E / 4 + 255) / 256 + 1;
    degree_kernel<<<eb4, 256>>>(src, dst, E);
    scan_kernel<<<1, 1024>>>(Nn);
    bin_kernel<<<eb4, 256>>>(src, dst, E);

    int mtiles = (Nn + 127) / 128;

    // Layer 1: 128 -> 128  (HMMA)  smem = (128 + 128) * 136 * 2 = 69632
    const int SM1 = (128 + 128) * (128 + 8) * 2;
    cudaFuncSetAttribute(gemm_mma_kernel<128, 128>,
                         cudaFuncAttributeMaxDynamicSharedMemorySize, SM1);
    gemm_mma_kernel<128, 128><<<mtiles, 256, SM1>>>(x, W1, t, Nn);
    gather_kernel<128, false><<<(Nn + 7) / 8, dim3(32, 8)>>>(t, b1, h, Nn);
    // Layer 2: 128 -> 64   (HMMA)  smem = (128 + 64) * 136 * 2 = 52224
    const int SM2 = (128 + 64) * (128 + 8) * 2;
    cudaFuncSetAttribute(gemm_mma_kernel<128, 64>,
                         cudaFuncAttributeMaxDynamicSharedMemorySize, SM2);
    gemm_mma_kernel<128, 64><<<mtiles, 256, SM2>>>(h, W2, t, Nn);
    gather_kernel<64, false><<<(Nn + 15) / 16, dim3(16, 16)>>>(t, b2, h, Nn);
    // Layer 3: 64 -> 32    (f32x2 SIMT)
    gemm_kernel<64, 32><<<dim3(mtiles, 1), 256>>>(h, W3, t, Nn);
    gather_kernel<32, false><<<(Nn + 31) / 32, dim3(8, 32)>>>(t, b3, h, Nn);
    // Layer 4: 32 -> 16
    gemm_kernel<32, 16><<<dim3(mtiles, 1), 256>>>(h, W4, t, Nn);
    gather_kernel<16, false><<<(Nn + 63) / 64, dim3(4, 64)>>>(t, b4, h, Nn);
    // Layer 5: 16 -> 16
    gemm_kernel<16, 16><<<dim3(mtiles, 1), 256>>>(h, W5, t, Nn);
    gather_kernel<16, true><<<(Nn + 63) / 64, dim3(4, 64)>>>(t, b5, (float*)d_out, Nn);
}

// round 14
// speedup vs baseline: 2.0899x; 1.0848x over previous
#include <cuda_runtime.h>
#include <cuda_fp16.h>
#include <cstdint>

#define MAXN  50000
#define MAXNP 50176          // 392 * 128, padded row count for safe tile loads
#define MAXE  800000
#define MAXF  128

typedef unsigned long long u64;

// ---------------- device scratch (allocation-free) ----------------
__device__ int    g_cnt_src[MAXN];
__device__ int    g_cnt_dst[MAXN];
__device__ float  g_norm_src[MAXN];
__device__ float  g_norm_dst[MAXN];
__device__ int    g_rowptr[MAXN + 1];
__device__ int    g_cursor[MAXN];
__device__ int    g_esrc[MAXE];
__device__ __half g_t[(size_t)MAXNP * MAXF];     // fp16 transformed features
__device__ __half g_h[(size_t)MAXNP * MAXF];     // fp16 activations
__device__ __half g_x16[(size_t)MAXNP * MAXF];   // fp16 copy of input x
__device__ __half g_wt[(128 + 64) * 136];        // WT1 [128][136] @0, WT2 [64][136] @17408

// ---------------- f32x2 packed math helpers ----------------
__device__ __forceinline__ u64 dup2(float v) {
    u64 r; asm("mov.b64 %0, {%1, %1};" : "=l"(r) : "f"(v)); return r;
}
__device__ __forceinline__ void fma2(u64& d, u64 a, u64 b) {
    asm("fma.rn.f32x2 %0, %1, %2, %0;" : "+l"(d) : "l"(a), "l"(b));
}
__device__ __forceinline__ void unpack2(u64 v, float& lo, float& hi) {
    asm("mov.b64 {%0, %1}, %2;" : "=f"(lo), "=f"(hi) : "l"(v));
}

// ---------------- hmma / cp.async helpers ----------------
__device__ __forceinline__ void mma16816(float* c, const unsigned* a, unsigned b0, unsigned b1) {
    asm volatile(
        "mma.sync.aligned.m16n8k16.row.col.f32.f16.f16.f32 "
        "{%0,%1,%2,%3}, {%4,%5,%6,%7}, {%8,%9}, {%0,%1,%2,%3};"
        : "+f"(c[0]), "+f"(c[1]), "+f"(c[2]), "+f"(c[3])
        : "r"(a[0]), "r"(a[1]), "r"(a[2]), "r"(a[3]), "r"(b0), "r"(b1));
}
__device__ __forceinline__ uint32_t smem_u32(const void* p) {
    uint32_t a;
    asm("{ .reg .u64 t; cvta.to.shared.u64 t, %1; cvt.u32.u64 %0, t; }" : "=r"(a) : "l"(p));
    return a;
}
__device__ __forceinline__ void cpa16(uint32_t dst, const void* src) {
    asm volatile("cp.async.cg.shared.global [%0], [%1], 16;" :: "r"(dst), "l"(src));
}

// ---------------- setup: x -> fp16, W1/W2 -> transposed padded fp16 ----------------
__global__ void convert_x_kernel(const float* __restrict__ x, int total4) {
    int i = blockIdx.x * blockDim.x + threadIdx.x;
    if (i < total4) {
        float4 v = *(const float4*)&x[i * 4];
        __half2 h0 = __floats2half2_rn(v.x, v.y);
        __half2 h1 = __floats2half2_rn(v.z, v.w);
        uint2 pk; pk.x = *(unsigned*)&h0; pk.y = *(unsigned*)&h1;
        *(uint2*)&g_x16[i * 4] = pk;
    }
}
__global__ void prep_w_kernel(const float* __restrict__ W1, const float* __restrict__ W2) {
    int i = blockIdx.x * blockDim.x + threadIdx.x;
    if (i < 16384) {                       // WT1: [n][k], stride 136
        int k = i >> 7, n = i & 127;
        g_wt[n * 136 + k] = __float2half(W1[k * 128 + n]);
    } else if (i < 16384 + 8192) {         // WT2
        int j = i - 16384;
        int k = j >> 6, n = j & 63;
        g_wt[17408 + n * 136 + k] = __float2half(W2[k * 64 + n]);
    }
}

// ---------------- degree histograms (4 edges / thread, int4 loads) ----------------
__global__ void degree_kernel(const int* __restrict__ src, const int* __restrict__ dst, int E) {
    int e0 = (blockIdx.x * blockDim.x + threadIdx.x) * 4;
    if (e0 + 3 < E) {
        int4 s = *(const int4*)&src[e0];
        int4 d = *(const int4*)&dst[e0];
        atomicAdd(&g_cnt_src[s.x], 1); atomicAdd(&g_cnt_src[s.y], 1);
        atomicAdd(&g_cnt_src[s.z], 1); atomicAdd(&g_cnt_src[s.w], 1);
        atomicAdd(&g_cnt_dst[d.x], 1); atomicAdd(&g_cnt_dst[d.y], 1);
        atomicAdd(&g_cnt_dst[d.z], 1); atomicAdd(&g_cnt_dst[d.w], 1);
    } else {
        for (int e = e0; e < E; e++) {
            atomicAdd(&g_cnt_src[src[e]], 1);
            atomicAdd(&g_cnt_dst[dst[e]], 1);
        }
    }
}

// ------- fused scan (4 elems/thread) + norms + cursor init -------
__global__ void scan_kernel(int Nn) {
    __shared__ int wsum[32];
    __shared__ int s_carry;
    int lane = threadIdx.x & 31;
    int wid  = threadIdx.x >> 5;
    if (threadIdx.x == 0) { s_carry = 0; g_rowptr[0] = 0; }
    __syncthreads();
    for (int base = 0; base < Nn; base += 4096) {
        int i0 = base + (int)threadIdx.x * 4;
        int4 v  = make_int4(0, 0, 0, 0);
        int4 cs = make_int4(0, 0, 0, 0);
        if (i0 + 3 < Nn) {
            v  = *(const int4*)&g_cnt_dst[i0];
            cs = *(const int4*)&g_cnt_src[i0];
        } else if (i0 < Nn) {
            for (int k = 0; k < 4 && i0 + k < Nn; k++) {
                ((int*)&v)[k]  = g_cnt_dst[i0 + k];
                ((int*)&cs)[k] = g_cnt_src[i0 + k];
            }
        }
        int s = v.x + v.y + v.z + v.w;
        int xs = s;
        #pragma unroll
        for (int off = 1; off < 32; off <<= 1) {
            int y = __shfl_up_sync(0xffffffffu, xs, off);
            if (lane >= off) xs += y;
        }
        if (lane == 31) wsum[wid] = xs;
        __syncthreads();
        if (wid == 0) {
            int w = wsum[lane];
            #pragma unroll
            for (int off = 1; off < 32; off <<= 1) {
                int y = __shfl_up_sync(0xffffffffu, w, off);
                if (lane >= off) w += y;
            }
            wsum[lane] = w;
        }
        __syncthreads();
        int p = s_carry + (xs - s) + (wid ? wsum[wid - 1] : 0);
        #pragma unroll
        for (int k = 0; k < 4; k++) {
            int idx = i0 + k;
            if (idx < Nn) {
                int vk  = ((int*)&v)[k];
                int csk = ((int*)&cs)[k];
                g_cursor[idx] = p;
                p += vk;
                g_rowptr[idx + 1] = p;
                if (csk < 1) csk = 1;
                int cd = vk < 1 ? 1 : vk;
                g_norm_src[idx] = rsqrtf((float)csk);
                g_norm_dst[idx] = rsqrtf((float)cd);
            }
        }
        __syncthreads();
        if (threadIdx.x == 0) s_carry += wsum[31];
        __syncthreads();
    }
}

// ---------------- bin edges by destination (4 edges / thread) ----------------
__global__ void bin_kernel(const int* __restrict__ src, const int* __restrict__ dst, int E) {
    int e0 = (blockIdx.x * blockDim.x + threadIdx.x) * 4;
    if (e0 + 3 < E) {
        int4 s = *(const int4*)&src[e0];
        int4 d = *(const int4*)&dst[e0];
        int p0 = atomicAdd(&g_cursor[d.x], 1);
        int p1 = atomicAdd(&g_cursor[d.y], 1);
        int p2 = atomicAdd(&g_cursor[d.z], 1);
        int p3 = atomicAdd(&g_cursor[d.w], 1);
        g_esrc[p0] = s.x; g_esrc[p1] = s.y; g_esrc[p2] = s.z; g_esrc[p3] = s.w;
    } else {
        for (int e = e0; e < E; e++) {
            int p = atomicAdd(&g_cursor[dst[e]], 1);
            g_esrc[p] = src[e];
        }
    }
}

// ------- HMMA GEMM (layers 1-2): cp.async fp16 staging, single wave -------
// A: fp16 activations [MAXNP][DIN]; B: pre-transposed padded WT in g_wt.
template <int DIN, int DOUT, int WT_OFF>
__global__ void __launch_bounds__(256, 3) gemm_mma_kernel(const __half* __restrict__ Ah,
                                                          __half* __restrict__ Cout, int Nn) {
    constexpr int SAK   = DIN + 8;          // 136 halfs, 272B row stride (conflict-free)
    constexpr int WN    = DOUT / 2;
    constexpr int NT_N  = WN / 8;
    constexpr int KSTEP = DIN / 16;
    constexpr int ACH   = DIN * 2 / 16;     // 16B chunks per A row (16)
    constexpr int BCH   = SAK * 2 / 16;     // 16B chunks per padded B row (17)

    extern __shared__ __half sm[];
    __half* sA = sm;                        // [128][SAK]
    __half* sB = sm + 128 * SAK;            // [DOUT][SAK]
    uint32_t sA_u = smem_u32(sA);
    uint32_t sB_u = smem_u32(sB);

    int tid  = threadIdx.x;
    int row0 = blockIdx.x * 128;

    // stage A via cp.async (buffer padded to MAXNP rows -> no row guard needed)
    for (int idx = tid; idx < 128 * ACH; idx += 256) {
        int r = idx / ACH, c = idx % ACH;
        cpa16(sA_u + (r * SAK) * 2 + c * 16,
              Ah + (size_t)(row0 + r) * DIN + c * 8);
    }
    // stage B (pre-padded WT rows, contiguous)
    for (int idx = tid; idx < DOUT * BCH; idx += 256) {
        int r = idx / BCH, c = idx % BCH;
        cpa16(sB_u + (r * SAK) * 2 + c * 16,
              g_wt + WT_OFF + r * SAK + c * 8);
    }
    asm volatile("cp.async.commit_group;");
    asm volatile("cp.async.wait_group 0;" ::: "memory");
    __syncthreads();

    int wid  = tid >> 5;
    int lane = tid & 31;
    int grp  = lane >> 2;
    int tig  = lane & 3;
    int wm   = wid & 3;
    int wn   = wid >> 2;
    int m_base = wm * 32;
    int n_base = wn * WN;

    float acc[2][NT_N][4];
    #pragma unroll
    for (int mt = 0; mt < 2; mt++)
        #pragma unroll
        for (int nt = 0; nt < NT_N; nt++)
            #pragma unroll
            for (int q = 0; q < 4; q++) acc[mt][nt][q] = 0.f;

    #pragma unroll
    for (int ks = 0; ks < KSTEP; ks++) {
        int k0 = ks * 16 + tig * 2;
        unsigned a[2][4];
        #pragma unroll
        for (int mt = 0; mt < 2; mt++) {
            int g = m_base + mt * 16 + grp;
            a[mt][0] = *(const unsigned*)&sA[g * SAK + k0];
            a[mt][1] = *(const unsigned*)&sA[(g + 8) * SAK + k0];
            a[mt][2] = *(const unsigned*)&sA[g * SAK + k0 + 8];
            a[mt][3] = *(const unsigned*)&sA[(g + 8) * SAK + k0 + 8];
        }
        #pragma unroll
        for (int nt = 0; nt < NT_N; nt++) {
            int n = n_base + nt * 8 + grp;
            unsigned b0 = *(const unsigned*)&sB[n * SAK + k0];
            unsigned b1 = *(const unsigned*)&sB[n * SAK + k0 + 8];
            mma16816(acc[0][nt], a[0], b0, b1);
            mma16816(acc[1][nt], a[1], b0, b1);
        }
    }

    #pragma unroll
    for (int mt = 0; mt < 2; mt++) {
        int g0 = row0 + m_base + mt * 16 + grp;
        int g1 = g0 + 8;
        float ns0 = (g0 < Nn) ? g_norm_src[g0] : 0.f;
        float ns1 = (g1 < Nn) ? g_norm_src[g1] : 0.f;
        #pragma unroll
        for (int nt = 0; nt < NT_N; nt++) {
            int col = n_base + nt * 8 + tig * 2;
            if (g0 < Nn) {
                __half2 h = __floats2half2_rn(acc[mt][nt][0] * ns0, acc[mt][nt][1] * ns0);
                *(__half2*)&Cout[(size_t)g0 * DOUT + col] = h;
            }
            if (g1 < Nn) {
                __half2 h = __floats2half2_rn(acc[mt][nt][2] * ns1, acc[mt][nt][3] * ns1);
                *(__half2*)&Cout[(size_t)g1 * DOUT + col] = h;
            }
        }
    }
}

// ------- f32x2 SIMT GEMM (layers 3-5): fp16 A, fp32 W -------
template <int DIN, int DOUT>
__global__ void __launch_bounds__(256) gemm_kernel(const __half* __restrict__ A,
                                                   const float* __restrict__ W,
                                                   __half* __restrict__ Cout, int Nn) {
    constexpr int BM = 128;
    constexpr int BN = (DOUT < 64) ? DOUT : 64;
    constexpr int BK = 16;
    constexpr int TN = 4;
    constexpr int TXC = BN / TN;
    constexpr int TYC = 256 / TXC;
    constexpr int TM = BM / TYC;
    constexpr int TP = TM / 2;

    __shared__ float sA[BK][BM + 4];
    __shared__ float sB[BK][BN];

    int row0 = blockIdx.x * BM;
    int col0 = blockIdx.y * BN;
    int tx = threadIdx.x % TXC;
    int ty = threadIdx.x / TXC;

    u64 acc[TP][TN];
    #pragma unroll
    for (int p = 0; p < TP; p++)
        #pragma unroll
        for (int j = 0; j < TN; j++) acc[p][j] = 0ull;

    for (int k0 = 0; k0 < DIN; k0 += BK) {
        #pragma unroll
        for (int idx = threadIdx.x; idx < BM * BK / 4; idx += 256) {
            int r = idx / (BK / 4);
            int c4 = (idx % (BK / 4)) * 4;
            uint2 pk = *(const uint2*)&A[(size_t)(row0 + r) * DIN + k0 + c4];   // padded buffer
            float2 v0 = __half22float2(*(__half2*)&pk.x);
            float2 v1 = __half22float2(*(__half2*)&pk.y);
            sA[c4 + 0][r] = v0.x; sA[c4 + 1][r] = v0.y;
            sA[c4 + 2][r] = v1.x; sA[c4 + 3][r] = v1.y;
        }
        #pragma unroll
        for (int idx = threadIdx.x; idx < BK * BN / 4; idx += 256) {
            int r = idx / (BN / 4);
            int c4 = (idx % (BN / 4)) * 4;
            *(float4*)&sB[r][c4] = *(const float4*)&W[(k0 + r) * DOUT + col0 + c4];
        }
        __syncthreads();
        #pragma unroll
        for (int kk = 0; kk < BK; kk++) {
            u64 a2[TP];
            #pragma unroll
            for (int p = 0; p < TP; p++)
                a2[p] = *(const u64*)&sA[kk][ty * TM + 2 * p];
            u64 b2[TN];
            #pragma unroll
            for (int j = 0; j < TN; j++)
                b2[j] = dup2(sB[kk][tx * TN + j]);
            #pragma unroll
            for (int p = 0; p < TP; p++)
                #pragma unroll
                for (int j = 0; j < TN; j++)
                    fma2(acc[p][j], a2[p], b2[j]);
        }
        __syncthreads();
    }
    #pragma unroll
    for (int p = 0; p < TP; p++) {
        float lo[TN], hi[TN];
        #pragma unroll
        for (int j = 0; j < TN; j++) unpack2(acc[p][j], lo[j], hi[j]);
        int gr = row0 + ty * TM + 2 * p;
        if (gr < Nn) {
            float ns = g_norm_src[gr];
            __half2 h0 = __floats2half2_rn(lo[0] * ns, lo[1] * ns);
            __half2 h1 = __floats2half2_rn(lo[2] * ns, lo[3] * ns);
            uint2 o; o.x = *(unsigned*)&h0; o.y = *(unsigned*)&h1;
            *(uint2*)&Cout[(size_t)gr * DOUT + col0 + tx * TN] = o;
        }
        if (gr + 1 < Nn) {
            float ns = g_norm_src[gr + 1];
            __half2 h0 = __floats2half2_rn(hi[0] * ns, hi[1] * ns);
            __half2 h1 = __floats2half2_rn(hi[2] * ns, hi[3] * ns);
            uint2 o; o.x = *(unsigned*)&h0; o.y = *(unsigned*)&h1;
            *(uint2*)&Cout[(size_t)(gr + 1) * DOUT + col0 + tx * TN] = o;
        }
    }
}

// ------- CSR gather (fp16 src) + norm_dst + bias + relu; fp16 or fp32 out -------
template <int D, bool HALF_OUT>
__global__ void __launch_bounds__(256) gather_kernel(const __half* __restrict__ t,
                                                     const float* __restrict__ bias,
                                                     void* __restrict__ outv, int Nn) {
    constexpr int TX = D / 4;
    int n = blockIdx.x * blockDim.y + threadIdx.y;
    if (n >= Nn) return;
    int f = threadIdx.x;
    const uint2* t4 = (const uint2*)t;
    int beg = g_rowptr[n], end = g_rowptr[n + 1];
    float4 acc = make_float4(0.f, 0.f, 0.f, 0.f);
    int j = beg;
    for (; j + 4 <= end; j += 4) {
        int s0 = g_esrc[j], s1 = g_esrc[j + 1], s2 = g_esrc[j + 2], s3 = g_esrc[j + 3];
        uint2 r0 = t4[s0 * TX + f];
        uint2 r1 = t4[s1 * TX + f];
        uint2 r2 = t4[s2 * TX + f];
        uint2 r3 = t4[s3 * TX + f];
        float2 a0 = __half22float2(*(__half2*)&r0.x), b0 = __half22float2(*(__half2*)&r0.y);
        float2 a1 = __half22float2(*(__half2*)&r1.x), b1 = __half22float2(*(__half2*)&r1.y);
        float2 a2 = __half22float2(*(__half2*)&r2.x), b2 = __half22float2(*(__half2*)&r2.y);
        float2 a3 = __half22float2(*(__half2*)&r3.x), b3 = __half22float2(*(__half2*)&r3.y);
        acc.x += (a0.x + a1.x) + (a2.x + a3.x);
        acc.y += (a0.y + a1.y) + (a2.y + a3.y);
        acc.z += (b0.x + b1.x) + (b2.x + b3.x);
        acc.w += (b0.y + b1.y) + (b2.y + b3.y);
    }
    for (; j < end; j++) {
        uint2 r = t4[g_esrc[j] * TX + f];
        float2 a = __half22float2(*(__half2*)&r.x), b = __half22float2(*(__half2*)&r.y);
        acc.x += a.x; acc.y += a.y; acc.z += b.x; acc.w += b.y;
    }
    float nd = g_norm_dst[n];
    float4 bb = ((const float4*)bias)[f];
    float4 o;
    o.x = fmaxf(fmaf(acc.x, nd, bb.x), 0.f);
    o.y = fmaxf(fmaf(acc.y, nd, bb.y), 0.f);
    o.z = fmaxf(fmaf(acc.z, nd, bb.z), 0.f);
    o.w = fmaxf(fmaf(acc.w, nd, bb.w), 0.f);
    if (HALF_OUT) {
        __half2 h0 = __floats2half2_rn(o.x, o.y);
        __half2 h1 = __floats2half2_rn(o.z, o.w);
        uint2 pk; pk.x = *(unsigned*)&h0; pk.y = *(unsigned*)&h1;
        ((uint2*)outv)[(size_t)n * TX + f] = pk;
    } else {
        ((float4*)outv)[(size_t)n * TX + f] = o;
    }
}

// ---------------- launch ----------------
extern "C" void kernel_launch(void* const* d_in, const int* in_sizes, int n_in,
                              void* d_out, int out_size) {
    const float* x  = (const float*)d_in[0];
    const int*   ed = (const int*)d_in[1];
    const float* W1 = (const float*)d_in[2];   const float* b1 = (const float*)d_in[3];
    const float* W2 = (const float*)d_in[4];   const float* b2 = (const float*)d_in[5];
    const float* W3 = (const float*)d_in[6];   const float* b3 = (const float*)d_in[7];
    const float* W4 = (const float*)d_in[8];   const float* b4 = (const float*)d_in[9];
    const float* W5 = (const float*)d_in[10];  const float* b5 = (const float*)d_in[11];

    const int Nn = in_sizes[0] / 128;
    const int E  = in_sizes[1] / 2;
    const int* src = ed;
    const int* dst = ed + E;

    void *pcs = nullptr, *pcd = nullptr, *pt = nullptr, *ph = nullptr, *px = nullptr;
    cudaGetSymbolAddress(&pcs, g_cnt_src);
    cudaGetSymbolAddress(&pcd, g_cnt_dst);
    cudaGetSymbolAddress(&pt,  g_t);
    cudaGetSymbolAddress(&ph,  g_h);
    cudaGetSymbolAddress(&px,  g_x16);
    __half* t   = (__half*)pt;
    __half* h   = (__half*)ph;
    __half* x16 = (__half*)px;

    cudaMemsetAsync(pcs, 0, Nn * sizeof(int), 0);
    cudaMemsetAsync(pcd, 0, Nn * sizeof(int), 0);

    int eb4 = (E / 4 + 255) / 256 + 1;
    convert_x_kernel<<<(Nn * 32 + 255) / 256, 256>>>(x, Nn * 32);
    prep_w_kernel<<<96, 256>>>(W1, W2);
    degree_kernel<<<eb4, 256>>>(src, dst, E);
    scan_kernel<<<1, 1024>>>(Nn);
    bin_kernel<<<eb4, 256>>>(src, dst, E);

    int mtiles = (Nn + 127) / 128;

    // Layer 1: 128 -> 128  (HMMA, cp.async)  smem = 256 * 272 = 69632
    const int SM1 = 256 * 272;
    cudaFuncSetAttribute(gemm_mma_kernel<128, 128, 0>,
                         cudaFuncAttributeMaxDynamicSharedMemorySize, SM1);
    gemm_mma_kernel<128, 128, 0><<<mtiles, 256, SM1>>>(x16, t, Nn);
    gather_kernel<128, true><<<(Nn + 7) / 8, dim3(32, 8)>>>(t, b1, h, Nn);
    // Layer 2: 128 -> 64   (HMMA, cp.async)  smem = 192 * 272 = 52224
    const int SM2 = 192 * 272;
    cudaFuncSetAttribute(gemm_mma_kernel<128, 64, 17408>,
                         cudaFuncAttributeMaxDynamicSharedMemorySize, SM2);
    gemm_mma_kernel<128, 64, 17408><<<mtiles, 256, SM2>>>(h, t, Nn);
    gather_kernel<64, true><<<(Nn + 15) / 16, dim3(16, 16)>>>(t, b2, h, Nn);
    // Layer 3: 64 -> 32    (f32x2 SIMT)
    gemm_kernel<64, 32><<<dim3(mtiles, 1), 256>>>(h, W3, t, Nn);
    gather_kernel<32, true><<<(Nn + 31) / 32, dim3(8, 32)>>>(t, b3, h, Nn);
    // Layer 4: 32 -> 16
    gemm_kernel<32, 16><<<dim3(mtiles, 1), 256>>>(h, W4, t, Nn);
    gather_kernel<16, true><<<(Nn + 63) / 64, dim3(4, 64)>>>(t, b4, h, Nn);
    // Layer 5: 16 -> 16
    gemm_kernel<16, 16><<<dim3(mtiles, 1), 256>>>(h, W5, t, Nn);
    gather_kernel<16, false><<<(Nn + 63) / 64, dim3(4, 64)>>>(t, b5, d_out, Nn);
}

// round 15
// speedup vs baseline: 2.6880x; 1.2862x over previous
#include <cuda_runtime.h>
#include <cuda_fp16.h>
#include <cstdint>

#define MAXN  50000
#define MAXNP 50176          // 392 * 128, padded row count for safe tile loads
#define MAXE  800000
#define MAXF  128
#define SCB   4096           // elements per scan block
#define NSB   ((MAXN + SCB - 1) / SCB)   // 13

typedef unsigned long long u64;

// ---------------- device scratch (allocation-free) ----------------
__device__ int    g_cnt_src[MAXN];
__device__ int    g_cnt_dst[MAXN];
__device__ float  g_norm_src[MAXN];
__device__ float  g_norm_dst[MAXN];
__device__ int    g_rowptr[MAXN + 1];
__device__ int    g_cursor[MAXN];
__device__ int    g_bsum[32];
__device__ int    g_boff[32];
__device__ int    g_esrc[MAXE];
__device__ __half g_t[(size_t)MAXNP * MAXF];     // fp16 transformed features
__device__ __half g_h[(size_t)MAXNP * MAXF];     // fp16 activations
__device__ __half g_x16[(size_t)MAXNP * MAXF];   // fp16 copy of input x
__device__ __half g_wt[(128 + 64) * 136];        // WT1 [128][136] @0, WT2 [64][136] @17408

// ---------------- f32x2 packed math helpers ----------------
__device__ __forceinline__ u64 dup2(float v) {
    u64 r; asm("mov.b64 %0, {%1, %1};" : "=l"(r) : "f"(v)); return r;
}
__device__ __forceinline__ void fma2(u64& d, u64 a, u64 b) {
    asm("fma.rn.f32x2 %0, %1, %2, %0;" : "+l"(d) : "l"(a), "l"(b));
}
__device__ __forceinline__ void unpack2(u64 v, float& lo, float& hi) {
    asm("mov.b64 {%0, %1}, %2;" : "=f"(lo), "=f"(hi) : "l"(v));
}

// ---------------- hmma / cp.async helpers ----------------
__device__ __forceinline__ void mma16816(float* c, const unsigned* a, unsigned b0, unsigned b1) {
    asm volatile(
        "mma.sync.aligned.m16n8k16.row.col.f32.f16.f16.f32 "
        "{%0,%1,%2,%3}, {%4,%5,%6,%7}, {%8,%9}, {%0,%1,%2,%3};"
        : "+f"(c[0]), "+f"(c[1]), "+f"(c[2]), "+f"(c[3])
        : "r"(a[0]), "r"(a[1]), "r"(a[2]), "r"(a[3]), "r"(b0), "r"(b1));
}
__device__ __forceinline__ uint32_t smem_u32(const void* p) {
    uint32_t a;
    asm("{ .reg .u64 t; cvta.to.shared.u64 t, %1; cvt.u32.u64 %0, t; }" : "=r"(a) : "l"(p));
    return a;
}
__device__ __forceinline__ void cpa16(uint32_t dst, const void* src) {
    asm volatile("cp.async.cg.shared.global [%0], [%1], 16;" :: "r"(dst), "l"(src));
}

// ---------------- setup: x -> fp16, W1/W2 -> transposed padded fp16 ----------------
__global__ void convert_x_kernel(const float* __restrict__ x, int total4) {
    int i = blockIdx.x * blockDim.x + threadIdx.x;
    if (i < total4) {
        float4 v = *(const float4*)&x[i * 4];
        __half2 h0 = __floats2half2_rn(v.x, v.y);
        __half2 h1 = __floats2half2_rn(v.z, v.w);
        uint2 pk; pk.x = *(unsigned*)&h0; pk.y = *(unsigned*)&h1;
        *(uint2*)&g_x16[i * 4] = pk;
    }
}
__global__ void prep_w_kernel(const float* __restrict__ W1, const float* __restrict__ W2) {
    int i = blockIdx.x * blockDim.x + threadIdx.x;
    if (i < 16384) {                       // WT1: [n][k], stride 136
        int k = i >> 7, n = i & 127;
        g_wt[n * 136 + k] = __float2half(W1[k * 128 + n]);
    } else if (i < 16384 + 8192) {         // WT2
        int j = i - 16384;
        int k = j >> 6, n = j & 63;
        g_wt[17408 + n * 136 + k] = __float2half(W2[k * 64 + n]);
    }
}

// ---------------- degree histograms (4 edges / thread, int4 loads) ----------------
__global__ void degree_kernel(const int* __restrict__ src, const int* __restrict__ dst, int E) {
    int e0 = (blockIdx.x * blockDim.x + threadIdx.x) * 4;
    if (e0 + 3 < E) {
        int4 s = *(const int4*)&src[e0];
        int4 d = *(const int4*)&dst[e0];
        atomicAdd(&g_cnt_src[s.x], 1); atomicAdd(&g_cnt_src[s.y], 1);
        atomicAdd(&g_cnt_src[s.z], 1); atomicAdd(&g_cnt_src[s.w], 1);
        atomicAdd(&g_cnt_dst[d.x], 1); atomicAdd(&g_cnt_dst[d.y], 1);
        atomicAdd(&g_cnt_dst[d.z], 1); atomicAdd(&g_cnt_dst[d.w], 1);
    } else {
        for (int e = e0; e < E; e++) {
            atomicAdd(&g_cnt_src[src[e]], 1);
            atomicAdd(&g_cnt_dst[dst[e]], 1);
        }
    }
}

// ------- scan phase 1: per-block local scan + norms + block totals -------
__global__ void scan_p1(int Nn) {
    __shared__ int wsum[32];
    int lane = threadIdx.x & 31;
    int wid  = threadIdx.x >> 5;
    int i0 = blockIdx.x * SCB + (int)threadIdx.x * 4;
    int4 v  = make_int4(0, 0, 0, 0);
    int4 cs = make_int4(0, 0, 0, 0);
    if (i0 + 3 < Nn) {
        v  = *(const int4*)&g_cnt_dst[i0];
        cs = *(const int4*)&g_cnt_src[i0];
    } else if (i0 < Nn) {
        for (int k = 0; k < 4 && i0 + k < Nn; k++) {
            ((int*)&v)[k]  = g_cnt_dst[i0 + k];
            ((int*)&cs)[k] = g_cnt_src[i0 + k];
        }
    }
    int s = v.x + v.y + v.z + v.w;
    int xs = s;
    #pragma unroll
    for (int off = 1; off < 32; off <<= 1) {
        int y = __shfl_up_sync(0xffffffffu, xs, off);
        if (lane >= off) xs += y;
    }
    if (lane == 31) wsum[wid] = xs;
    __syncthreads();
    if (wid == 0) {
        int w = wsum[lane];
        #pragma unroll
        for (int off = 1; off < 32; off <<= 1) {
            int y = __shfl_up_sync(0xffffffffu, w, off);
            if (lane >= off) w += y;
        }
        wsum[lane] = w;
    }
    __syncthreads();
    int p = (xs - s) + (wid ? wsum[wid - 1] : 0);   // local exclusive prefix
    #pragma unroll
    for (int k = 0; k < 4; k++) {
        int idx = i0 + k;
        if (idx < Nn) {
            int vk  = ((int*)&v)[k];
            int csk = ((int*)&cs)[k];
            g_cursor[idx] = p;
            p += vk;
            g_rowptr[idx + 1] = p;
            if (csk < 1) csk = 1;
            int cd = vk < 1 ? 1 : vk;
            g_norm_src[idx] = rsqrtf((float)csk);
            g_norm_dst[idx] = rsqrtf((float)cd);
        }
    }
    if (threadIdx.x == 0) g_bsum[blockIdx.x] = wsum[31];
}

// ------- scan phase 2: exclusive scan of block totals (1 warp) -------
__global__ void scan_p2(int nb) {
    int lane = threadIdx.x;
    int v = (lane < nb) ? g_bsum[lane] : 0;
    int x = v;
    #pragma unroll
    for (int off = 1; off < 32; off <<= 1) {
        int y = __shfl_up_sync(0xffffffffu, x, off);
        if (lane >= off) x += y;
    }
    if (lane < nb) g_boff[lane] = x - v;
}

// ------- scan phase 3: add block offsets -------
__global__ void scan_p3(int Nn) {
    int off = g_boff[blockIdx.x];
    int i0 = blockIdx.x * SCB + (int)threadIdx.x * 4;
    #pragma unroll
    for (int k = 0; k < 4; k++) {
        int idx = i0 + k;
        if (idx < Nn) {
            g_cursor[idx] += off;
            g_rowptr[idx + 1] += off;
        }
    }
    if (blockIdx.x == 0 && threadIdx.x == 0) g_rowptr[0] = 0;
}

// ---------------- bin edges by destination (4 edges / thread) ----------------
__global__ void bin_kernel(const int* __restrict__ src, const int* __restrict__ dst, int E) {
    int e0 = (blockIdx.x * blockDim.x + threadIdx.x) * 4;
    if (e0 + 3 < E) {
        int4 s = *(const int4*)&src[e0];
        int4 d = *(const int4*)&dst[e0];
        int p0 = atomicAdd(&g_cursor[d.x], 1);
        int p1 = atomicAdd(&g_cursor[d.y], 1);
        int p2 = atomicAdd(&g_cursor[d.z], 1);
        int p3 = atomicAdd(&g_cursor[d.w], 1);
        g_esrc[p0] = s.x; g_esrc[p1] = s.y; g_esrc[p2] = s.z; g_esrc[p3] = s.w;
    } else {
        for (int e = e0; e < E; e++) {
            int p = atomicAdd(&g_cursor[dst[e]], 1);
            g_esrc[p] = src[e];
        }
    }
}

// ------- HMMA GEMM (layers 1-2): cp.async fp16 staging, single wave -------
template <int DIN, int DOUT, int WT_OFF>
__global__ void __launch_bounds__(256, 3) gemm_mma_kernel(const __half* __restrict__ Ah,
                                                          __half* __restrict__ Cout, int Nn) {
    constexpr int SAK   = DIN + 8;          // 136 halfs, 272B row stride (conflict-free)
    constexpr int WN    = DOUT / 2;
    constexpr int NT_N  = WN / 8;
    constexpr int KSTEP = DIN / 16;
    constexpr int ACH   = DIN * 2 / 16;     // 16B chunks per A row
    constexpr int BCH   = SAK * 2 / 16;     // 16B chunks per padded B row

    extern __shared__ __half sm[];
    __half* sA = sm;                        // [128][SAK]
    __half* sB = sm + 128 * SAK;            // [DOUT][SAK]
    uint32_t sA_u = smem_u32(sA);
    uint32_t sB_u = smem_u32(sB);

    int tid  = threadIdx.x;
    int row0 = blockIdx.x * 128;

    for (int idx = tid; idx < 128 * ACH; idx += 256) {
        int r = idx / ACH, c = idx % ACH;
        cpa16(sA_u + (r * SAK) * 2 + c * 16,
              Ah + (size_t)(row0 + r) * DIN + c * 8);
    }
    for (int idx = tid; idx < DOUT * BCH; idx += 256) {
        int r = idx / BCH, c = idx % BCH;
        cpa16(sB_u + (r * SAK) * 2 + c * 16,
              g_wt + WT_OFF + r * SAK + c * 8);
    }
    asm volatile("cp.async.commit_group;");
    asm volatile("cp.async.wait_group 0;" ::: "memory");
    __syncthreads();

    int wid  = tid >> 5;
    int lane = tid & 31;
    int grp  = lane >> 2;
    int tig  = lane & 3;
    int wm   = wid & 3;
    int wn   = wid >> 2;
    int m_base = wm * 32;
    int n_base = wn * WN;

    float acc[2][NT_N][4];
    #pragma unroll
    for (int mt = 0; mt < 2; mt++)
        #pragma unroll
        for (int nt = 0; nt < NT_N; nt++)
            #pragma unroll
            for (int q = 0; q < 4; q++) acc[mt][nt][q] = 0.f;

    #pragma unroll
    for (int ks = 0; ks < KSTEP; ks++) {
        int k0 = ks * 16 + tig * 2;
        unsigned a[2][4];
        #pragma unroll
        for (int mt = 0; mt < 2; mt++) {
            int g = m_base + mt * 16 + grp;
            a[mt][0] = *(const unsigned*)&sA[g * SAK + k0];
            a[mt][1] = *(const unsigned*)&sA[(g + 8) * SAK + k0];
            a[mt][2] = *(const unsigned*)&sA[g * SAK + k0 + 8];
            a[mt][3] = *(const unsigned*)&sA[(g + 8) * SAK + k0 + 8];
        }
        #pragma unroll
        for (int nt = 0; nt < NT_N; nt++) {
            int n = n_base + nt * 8 + grp;
            unsigned b0 = *(const unsigned*)&sB[n * SAK + k0];
            unsigned b1 = *(const unsigned*)&sB[n * SAK + k0 + 8];
            mma16816(acc[0][nt], a[0], b0, b1);
            mma16816(acc[1][nt], a[1], b0, b1);
        }
    }

    #pragma unroll
    for (int mt = 0; mt < 2; mt++) {
        int g0 = row0 + m_base + mt * 16 + grp;
        int g1 = g0 + 8;
        float ns0 = (g0 < Nn) ? g_norm_src[g0] : 0.f;
        float ns1 = (g1 < Nn) ? g_norm_src[g1] : 0.f;
        #pragma unroll
        for (int nt = 0; nt < NT_N; nt++) {
            int col = n_base + nt * 8 + tig * 2;
            if (g0 < Nn) {
                __half2 h = __floats2half2_rn(acc[mt][nt][0] * ns0, acc[mt][nt][1] * ns0);
                *(__half2*)&Cout[(size_t)g0 * DOUT + col] = h;
            }
            if (g1 < Nn) {
                __half2 h = __floats2half2_rn(acc[mt][nt][2] * ns1, acc[mt][nt][3] * ns1);
                *(__half2*)&Cout[(size_t)g1 * DOUT + col] = h;
            }
        }
    }
}

// ------- f32x2 SIMT GEMM (layers 3-5): fp16 A, fp32 W -------
template <int DIN, int DOUT>
__global__ void __launch_bounds__(256) gemm_kernel(const __half* __restrict__ A,
                                                   const float* __restrict__ W,
                                                   __half* __restrict__ Cout, int Nn) {
    constexpr int BM = 128;
    constexpr int BN = (DOUT < 64) ? DOUT : 64;
    constexpr int BK = 16;
    constexpr int TN = 4;
    constexpr int TXC = BN / TN;
    constexpr int TYC = 256 / TXC;
    constexpr int TM = BM / TYC;
    constexpr int TP = TM / 2;

    __shared__ float sA[BK][BM + 4];
    __shared__ float sB[BK][BN];

    int row0 = blockIdx.x * BM;
    int col0 = blockIdx.y * BN;
    int tx = threadIdx.x % TXC;
    int ty = threadIdx.x / TXC;

    u64 acc[TP][TN];
    #pragma unroll
    for (int p = 0; p < TP; p++)
        #pragma unroll
        for (int j = 0; j < TN; j++) acc[p][j] = 0ull;

    for (int k0 = 0; k0 < DIN; k0 += BK) {
        #pragma unroll
        for (int idx = threadIdx.x; idx < BM * BK / 4; idx += 256) {
            int r = idx / (BK / 4);
            int c4 = (idx % (BK / 4)) * 4;
            uint2 pk = *(const uint2*)&A[(size_t)(row0 + r) * DIN + k0 + c4];
            float2 v0 = __half22float2(*(__half2*)&pk.x);
            float2 v1 = __half22float2(*(__half2*)&pk.y);
            sA[c4 + 0][r] = v0.x; sA[c4 + 1][r] = v0.y;
            sA[c4 + 2][r] = v1.x; sA[c4 + 3][r] = v1.y;
        }
        #pragma unroll
        for (int idx = threadIdx.x; idx < BK * BN / 4; idx += 256) {
            int r = idx / (BN / 4);
            int c4 = (idx % (BN / 4)) * 4;
            *(float4*)&sB[r][c4] = *(const float4*)&W[(k0 + r) * DOUT + col0 + c4];
        }
        __syncthreads();
        #pragma unroll
        for (int kk = 0; kk < BK; kk++) {
            u64 a2[TP];
            #pragma unroll
            for (int p = 0; p < TP; p++)
                a2[p] = *(const u64*)&sA[kk][ty * TM + 2 * p];
            u64 b2[TN];
            #pragma unroll
            for (int j = 0; j < TN; j++)
                b2[j] = dup2(sB[kk][tx * TN + j]);
            #pragma unroll
            for (int p = 0; p < TP; p++)
                #pragma unroll
                for (int j = 0; j < TN; j++)
                    fma2(acc[p][j], a2[p], b2[j]);
        }
        __syncthreads();
    }
    #pragma unroll
    for (int p = 0; p < TP; p++) {
        float lo[TN], hi[TN];
        #pragma unroll
        for (int j = 0; j < TN; j++) unpack2(acc[p][j], lo[j], hi[j]);
        int gr = row0 + ty * TM + 2 * p;
        if (gr < Nn) {
            float ns = g_norm_src[gr];
            __half2 h0 = __floats2half2_rn(lo[0] * ns, lo[1] * ns);
            __half2 h1 = __floats2half2_rn(lo[2] * ns, lo[3] * ns);
            uint2 o; o.x = *(unsigned*)&h0; o.y = *(unsigned*)&h1;
            *(uint2*)&Cout[(size_t)gr * DOUT + col0 + tx * TN] = o;
        }
        if (gr + 1 < Nn) {
            float ns = g_norm_src[gr + 1];
            __half2 h0 = __floats2half2_rn(hi[0] * ns, hi[1] * ns);
            __half2 h1 = __floats2half2_rn(hi[2] * ns, hi[3] * ns);
            uint2 o; o.x = *(unsigned*)&h0; o.y = *(unsigned*)&h1;
            *(uint2*)&Cout[(size_t)(gr + 1) * DOUT + col0 + tx * TN] = o;
        }
    }
}

// ------- CSR gather (fp16 src) + norm_dst + bias + relu; fp16 or fp32 out -------
template <int D, bool HALF_OUT>
__global__ void __launch_bounds__(256) gather_kernel(const __half* __restrict__ t,
                                                     const float* __restrict__ bias,
                                                     void* __restrict__ outv, int Nn) {
    constexpr int TX = D / 4;
    int n = blockIdx.x * blockDim.y + threadIdx.y;
    if (n >= Nn) return;
    int f = threadIdx.x;
    const uint2* t4 = (const uint2*)t;
    int beg = g_rowptr[n], end = g_rowptr[n + 1];
    float4 acc = make_float4(0.f, 0.f, 0.f, 0.f);
    int j = beg;
    for (; j + 4 <= end; j += 4) {
        int s0 = g_esrc[j], s1 = g_esrc[j + 1], s2 = g_esrc[j + 2], s3 = g_esrc[j + 3];
        uint2 r0 = t4[s0 * TX + f];
        uint2 r1 = t4[s1 * TX + f];
        uint2 r2 = t4[s2 * TX + f];
        uint2 r3 = t4[s3 * TX + f];
        float2 a0 = __half22float2(*(__half2*)&r0.x), b0 = __half22float2(*(__half2*)&r0.y);
        float2 a1 = __half22float2(*(__half2*)&r1.x), b1 = __half22float2(*(__half2*)&r1.y);
        float2 a2 = __half22float2(*(__half2*)&r2.x), b2 = __half22float2(*(__half2*)&r2.y);
        float2 a3 = __half22float2(*(__half2*)&r3.x), b3 = __half22float2(*(__half2*)&r3.y);
        acc.x += (a0.x + a1.x) + (a2.x + a3.x);
        acc.y += (a0.y + a1.y) + (a2.y + a3.y);
        acc.z += (b0.x + b1.x) + (b2.x + b3.x);
        acc.w += (b0.y + b1.y) + (b2.y + b3.y);
    }
    for (; j < end; j++) {
        uint2 r = t4[g_esrc[j] * TX + f];
        float2 a = __half22float2(*(__half2*)&r.x), b = __half22float2(*(__half2*)&r.y);
        acc.x += a.x; acc.y += a.y; acc.z += b.x; acc.w += b.y;
    }
    float nd = g_norm_dst[n];
    float4 bb = ((const float4*)bias)[f];
    float4 o;
    o.x = fmaxf(fmaf(acc.x, nd, bb.x), 0.f);
    o.y = fmaxf(fmaf(acc.y, nd, bb.y), 0.f);
    o.z = fmaxf(fmaf(acc.z, nd, bb.z), 0.f);
    o.w = fmaxf(fmaf(acc.w, nd, bb.w), 0.f);
    if (HALF_OUT) {
        __half2 h0 = __floats2half2_rn(o.x, o.y);
        __half2 h1 = __floats2half2_rn(o.z, o.w);
        uint2 pk; pk.x = *(unsigned*)&h0; pk.y = *(unsigned*)&h1;
        ((uint2*)outv)[(size_t)n * TX + f] = pk;
    } else {
        ((float4*)outv)[(size_t)n * TX + f] = o;
    }
}

// ---------------- launch ----------------
extern "C" void kernel_launch(void* const* d_in, const int* in_sizes, int n_in,
                              void* d_out, int out_size) {
    const float* x  = (const float*)d_in[0];
    const int*   ed = (const int*)d_in[1];
    const float* W1 = (const float*)d_in[2];   const float* b1 = (const float*)d_in[3];
    const float* W2 = (const float*)d_in[4];   const float* b2 = (const float*)d_in[5];
    const float* W3 = (const float*)d_in[6];   const float* b3 = (const float*)d_in[7];
    const float* W4 = (const float*)d_in[8];   const float* b4 = (const float*)d_in[9];
    const float* W5 = (const float*)d_in[10];  const float* b5 = (const float*)d_in[11];

    const int Nn = in_sizes[0] / 128;
    const int E  = in_sizes[1] / 2;
    const int* src = ed;
    const int* dst = ed + E;

    void *pcs = nullptr, *pcd = nullptr, *pt = nullptr, *ph = nullptr, *px = nullptr;
    cudaGetSymbolAddress(&pcs, g_cnt_src);
    cudaGetSymbolAddress(&pcd, g_cnt_dst);
    cudaGetSymbolAddress(&pt,  g_t);
    cudaGetSymbolAddress(&ph,  g_h);
    cudaGetSymbolAddress(&px,  g_x16);
    __half* t   = (__half*)pt;
    __half* h   = (__half*)ph;
    __half* x16 = (__half*)px;

    cudaMemsetAsync(pcs, 0, Nn * sizeof(int), 0);
    cudaMemsetAsync(pcd, 0, Nn * sizeof(int), 0);

    int eb4 = (E / 4 + 255) / 256 + 1;
    int nsb = (Nn + SCB - 1) / SCB;
    convert_x_kernel<<<(Nn * 32 + 255) / 256, 256>>>(x, Nn * 32);
    prep_w_kernel<<<96, 256>>>(W1, W2);
    degree_kernel<<<eb4, 256>>>(src, dst, E);
    scan_p1<<<nsb, 1024>>>(Nn);
    scan_p2<<<1, 32>>>(nsb);
    scan_p3<<<nsb, 1024>>>(Nn);
    bin_kernel<<<eb4, 256>>>(src, dst, E);

    int mtiles = (Nn + 127) / 128;

    // Layer 1: 128 -> 128  (HMMA, cp.async)  smem = 256 * 272 = 69632
    const int SM1 = 256 * 272;
    cudaFuncSetAttribute(gemm_mma_kernel<128, 128, 0>,
                         cudaFuncAttributeMaxDynamicSharedMemorySize, SM1);
    gemm_mma_kernel<128, 128, 0><<<mtiles, 256, SM1>>>(x16, t, Nn);
    gather_kernel<128, true><<<(Nn + 7) / 8, dim3(32, 8)>>>(t, b1, h, Nn);
    // Layer 2: 128 -> 64   (HMMA, cp.async)  smem = 192 * 272 = 52224
    const int SM2 = 192 * 272;
    cudaFuncSetAttribute(gemm_mma_kernel<128, 64, 17408>,
                         cudaFuncAttributeMaxDynamicSharedMemorySize, SM2);
    gemm_mma_kernel<128, 64, 17408><<<mtiles, 256, SM2>>>(h, t, Nn);
    gather_kernel<64, true><<<(Nn + 15) / 16, dim3(16, 16)>>>(t, b2, h, Nn);
    // Layer 3: 64 -> 32    (f32x2 SIMT)
    gemm_kernel<64, 32><<<dim3(mtiles, 1), 256>>>(h, W3, t, Nn);
    gather_kernel<32, true><<<(Nn + 31) / 32, dim3(8, 32)>>>(t, b3, h, Nn);
    // Layer 4: 32 -> 16
    gemm_kernel<32, 16><<<dim3(mtiles, 1), 256>>>(h, W4, t, Nn);
    gather_kernel<16, true><<<(Nn + 63) / 64, dim3(4, 64)>>>(t, b4, h, Nn);
    // Layer 5: 16 -> 16
    gemm_kernel<16, 16><<<dim3(mtiles, 1), 256>>>(h, W5, t, Nn);
    gather_kernel<16, false><<<(Nn + 63) / 64, dim3(4, 64)>>>(t, b5, d_out, Nn);
}

// round 16
// speedup vs baseline: 2.9424x; 1.0946x over previous
#include <cuda_runtime.h>
#include <cuda_fp16.h>
#include <cstdint>

#define MAXN  50000
#define MAXNP 50176          // 392 * 128, padded row count for safe tile loads
#define MAXE  800000
#define MAXF  128
#define SCB   4096           // elements per scan block

typedef unsigned long long u64;

// ---------------- device scratch (allocation-free) ----------------
__device__ int    g_cnt_src[MAXN];
__device__ int    g_cnt_dst[MAXN];
__device__ float  g_norm_src[MAXN];
__device__ float  g_norm_dst[MAXN];
__device__ int    g_rowptr[MAXN + 1];
__device__ int    g_cursor[MAXN];
__device__ int    g_bsum[32];
__device__ int    g_boff[32];
__device__ int    g_esrc[MAXE];
__device__ __half g_t[(size_t)MAXNP * MAXF];     // fp16 transformed features
__device__ __half g_h[(size_t)MAXNP * MAXF];     // fp16 activations
__device__ __half g_x16[(size_t)MAXNP * MAXF];   // fp16 copy of input x
__device__ __half g_wt[(128 + 64) * 136];        // WT1 [128][136] @0, WT2 [64][136] @17408

// ---------------- f32x2 packed math helpers ----------------
__device__ __forceinline__ u64 dup2(float v) {
    u64 r; asm("mov.b64 %0, {%1, %1};" : "=l"(r) : "f"(v)); return r;
}
__device__ __forceinline__ void fma2(u64& d, u64 a, u64 b) {
    asm("fma.rn.f32x2 %0, %1, %2, %0;" : "+l"(d) : "l"(a), "l"(b));
}
__device__ __forceinline__ void unpack2(u64 v, float& lo, float& hi) {
    asm("mov.b64 {%0, %1}, %2;" : "=f"(lo), "=f"(hi) : "l"(v));
}

// ---------------- hmma / cp.async helpers ----------------
__device__ __forceinline__ void mma16816(float* c, const unsigned* a, unsigned b0, unsigned b1) {
    asm volatile(
        "mma.sync.aligned.m16n8k16.row.col.f32.f16.f16.f32 "
        "{%0,%1,%2,%3}, {%4,%5,%6,%7}, {%8,%9}, {%0,%1,%2,%3};"
        : "+f"(c[0]), "+f"(c[1]), "+f"(c[2]), "+f"(c[3])
        : "r"(a[0]), "r"(a[1]), "r"(a[2]), "r"(a[3]), "r"(b0), "r"(b1));
}
__device__ __forceinline__ uint32_t smem_u32(const void* p) {
    uint32_t a;
    asm("{ .reg .u64 t; cvta.to.shared.u64 t, %1; cvt.u32.u64 %0, t; }" : "=r"(a) : "l"(p));
    return a;
}
__device__ __forceinline__ void cpa16(uint32_t dst, const void* src) {
    asm volatile("cp.async.cg.shared.global [%0], [%1], 16;" :: "r"(dst), "l"(src));
}

// ------- fused setup: x -> fp16 AND W1/W2 -> transposed padded fp16 -------
__global__ void setup_kernel(const float* __restrict__ x, int cvb,
                             const float* __restrict__ W1, const float* __restrict__ W2) {
    int b = blockIdx.x;
    if (b < cvb) {
        int i = b * blockDim.x + threadIdx.x;           // float4 index into x
        float4 v = *(const float4*)&x[(size_t)i * 4];
        __half2 h0 = __floats2half2_rn(v.x, v.y);
        __half2 h1 = __floats2half2_rn(v.z, v.w);
        uint2 pk; pk.x = *(unsigned*)&h0; pk.y = *(unsigned*)&h1;
        *(uint2*)&g_x16[(size_t)i * 4] = pk;
    } else {
        int i = (b - cvb) * blockDim.x + threadIdx.x;
        if (i < 16384) {                                // WT1: [n][k], stride 136
            int k = i >> 7, n = i & 127;
            g_wt[n * 136 + k] = __float2half(W1[k * 128 + n]);
        } else if (i < 16384 + 8192) {                  // WT2
            int j = i - 16384;
            int k = j >> 6, n = j & 63;
            g_wt[17408 + n * 136 + k] = __float2half(W2[k * 64 + n]);
        }
    }
}

// ---------------- degree histograms (8 edges / thread) ----------------
__global__ void degree_kernel(const int* __restrict__ src, const int* __restrict__ dst, int E) {
    int e0 = (blockIdx.x * blockDim.x + threadIdx.x) * 8;
    if (e0 + 7 < E) {
        int4 s0 = *(const int4*)&src[e0];
        int4 s1 = *(const int4*)&src[e0 + 4];
        int4 d0 = *(const int4*)&dst[e0];
        int4 d1 = *(const int4*)&dst[e0 + 4];
        atomicAdd(&g_cnt_src[s0.x], 1); atomicAdd(&g_cnt_src[s0.y], 1);
        atomicAdd(&g_cnt_src[s0.z], 1); atomicAdd(&g_cnt_src[s0.w], 1);
        atomicAdd(&g_cnt_src[s1.x], 1); atomicAdd(&g_cnt_src[s1.y], 1);
        atomicAdd(&g_cnt_src[s1.z], 1); atomicAdd(&g_cnt_src[s1.w], 1);
        atomicAdd(&g_cnt_dst[d0.x], 1); atomicAdd(&g_cnt_dst[d0.y], 1);
        atomicAdd(&g_cnt_dst[d0.z], 1); atomicAdd(&g_cnt_dst[d0.w], 1);
        atomicAdd(&g_cnt_dst[d1.x], 1); atomicAdd(&g_cnt_dst[d1.y], 1);
        atomicAdd(&g_cnt_dst[d1.z], 1); atomicAdd(&g_cnt_dst[d1.w], 1);
    } else {
        for (int e = e0; e < E; e++) {
            atomicAdd(&g_cnt_src[src[e]], 1);
            atomicAdd(&g_cnt_dst[dst[e]], 1);
        }
    }
}

// ------- scan phase 1: per-block local scan + norms + block totals -------
__global__ void scan_p1(int Nn) {
    __shared__ int wsum[32];
    int lane = threadIdx.x & 31;
    int wid  = threadIdx.x >> 5;
    int i0 = blockIdx.x * SCB + (int)threadIdx.x * 4;
    int4 v  = make_int4(0, 0, 0, 0);
    int4 cs = make_int4(0, 0, 0, 0);
    if (i0 + 3 < Nn) {
        v  = *(const int4*)&g_cnt_dst[i0];
        cs = *(const int4*)&g_cnt_src[i0];
    } else if (i0 < Nn) {
        for (int k = 0; k < 4 && i0 + k < Nn; k++) {
            ((int*)&v)[k]  = g_cnt_dst[i0 + k];
            ((int*)&cs)[k] = g_cnt_src[i0 + k];
        }
    }
    int s = v.x + v.y + v.z + v.w;
    int xs = s;
    #pragma unroll
    for (int off = 1; off < 32; off <<= 1) {
        int y = __shfl_up_sync(0xffffffffu, xs, off);
        if (lane >= off) xs += y;
    }
    if (lane == 31) wsum[wid] = xs;
    __syncthreads();
    if (wid == 0) {
        int w = wsum[lane];
        #pragma unroll
        for (int off = 1; off < 32; off <<= 1) {
            int y = __shfl_up_sync(0xffffffffu, w, off);
            if (lane >= off) w += y;
        }
        wsum[lane] = w;
    }
    __syncthreads();
    int p = (xs - s) + (wid ? wsum[wid - 1] : 0);   // local exclusive prefix
    #pragma unroll
    for (int k = 0; k < 4; k++) {
        int idx = i0 + k;
        if (idx < Nn) {
            int vk  = ((int*)&v)[k];
            int csk = ((int*)&cs)[k];
            g_cursor[idx] = p;
            p += vk;
            g_rowptr[idx + 1] = p;
            if (csk < 1) csk = 1;
            int cd = vk < 1 ? 1 : vk;
            g_norm_src[idx] = rsqrtf((float)csk);
            g_norm_dst[idx] = rsqrtf((float)cd);
        }
    }
    if (threadIdx.x == 0) g_bsum[blockIdx.x] = wsum[31];
}

// ------- scan phase 2: exclusive scan of block totals (1 warp) -------
__global__ void scan_p2(int nb) {
    int lane = threadIdx.x;
    int v = (lane < nb) ? g_bsum[lane] : 0;
    int x = v;
    #pragma unroll
    for (int off = 1; off < 32; off <<= 1) {
        int y = __shfl_up_sync(0xffffffffu, x, off);
        if (lane >= off) x += y;
    }
    if (lane < nb) g_boff[lane] = x - v;
}

// ------- scan phase 3: add block offsets -------
__global__ void scan_p3(int Nn) {
    int off = g_boff[blockIdx.x];
    int i0 = blockIdx.x * SCB + (int)threadIdx.x * 4;
    #pragma unroll
    for (int k = 0; k < 4; k++) {
        int idx = i0 + k;
        if (idx < Nn) {
            g_cursor[idx] += off;
            g_rowptr[idx + 1] += off;
        }
    }
    if (blockIdx.x == 0 && threadIdx.x == 0) g_rowptr[0] = 0;
}

// ---------------- bin edges by destination (8 edges / thread) ----------------
__global__ void bin_kernel(const int* __restrict__ src, const int* __restrict__ dst, int E) {
    int e0 = (blockIdx.x * blockDim.x + threadIdx.x) * 8;
    if (e0 + 7 < E) {
        int4 s0 = *(const int4*)&src[e0];
        int4 s1 = *(const int4*)&src[e0 + 4];
        int4 d0 = *(const int4*)&dst[e0];
        int4 d1 = *(const int4*)&dst[e0 + 4];
        int p0 = atomicAdd(&g_cursor[d0.x], 1);
        int p1 = atomicAdd(&g_cursor[d0.y], 1);
        int p2 = atomicAdd(&g_cursor[d0.z], 1);
        int p3 = atomicAdd(&g_cursor[d0.w], 1);
        int p4 = atomicAdd(&g_cursor[d1.x], 1);
        int p5 = atomicAdd(&g_cursor[d1.y], 1);
        int p6 = atomicAdd(&g_cursor[d1.z], 1);
        int p7 = atomicAdd(&g_cursor[d1.w], 1);
        g_esrc[p0] = s0.x; g_esrc[p1] = s0.y; g_esrc[p2] = s0.z; g_esrc[p3] = s0.w;
        g_esrc[p4] = s1.x; g_esrc[p5] = s1.y; g_esrc[p6] = s1.z; g_esrc[p7] = s1.w;
    } else {
        for (int e = e0; e < E; e++) {
            int p = atomicAdd(&g_cursor[dst[e]], 1);
            g_esrc[p] = src[e];
        }
    }
}

// ------- HMMA GEMM (layers 1-2): cp.async fp16 staging, single wave -------
template <int DIN, int DOUT, int WT_OFF>
__global__ void __launch_bounds__(256, 3) gemm_mma_kernel(const __half* __restrict__ Ah,
                                                          __half* __restrict__ Cout, int Nn) {
    constexpr int SAK   = DIN + 8;          // 136 halfs, 272B row stride (conflict-free)
    constexpr int WN    = DOUT / 2;
    constexpr int NT_N  = WN / 8;
    constexpr int KSTEP = DIN / 16;
    constexpr int ACH   = DIN * 2 / 16;
    constexpr int BCH   = SAK * 2 / 16;

    extern __shared__ __half sm[];
    __half* sA = sm;                        // [128][SAK]
    __half* sB = sm + 128 * SAK;            // [DOUT][SAK]
    uint32_t sA_u = smem_u32(sA);
    uint32_t sB_u = smem_u32(sB);

    int tid  = threadIdx.x;
    int row0 = blockIdx.x * 128;

    for (int idx = tid; idx < 128 * ACH; idx += 256) {
        int r = idx / ACH, c = idx % ACH;
        cpa16(sA_u + (r * SAK) * 2 + c * 16,
              Ah + (size_t)(row0 + r) * DIN + c * 8);
    }
    for (int idx = tid; idx < DOUT * BCH; idx += 256) {
        int r = idx / BCH, c = idx % BCH;
        cpa16(sB_u + (r * SAK) * 2 + c * 16,
              g_wt + WT_OFF + r * SAK + c * 8);
    }
    asm volatile("cp.async.commit_group;");
    asm volatile("cp.async.wait_group 0;" ::: "memory");
    __syncthreads();

    int wid  = tid >> 5;
    int lane = tid & 31;
    int grp  = lane >> 2;
    int tig  = lane & 3;
    int wm   = wid & 3;
    int wn   = wid >> 2;
    int m_base = wm * 32;
    int n_base = wn * WN;

    float acc[2][NT_N][4];
    #pragma unroll
    for (int mt = 0; mt < 2; mt++)
        #pragma unroll
        for (int nt = 0; nt < NT_N; nt++)
            #pragma unroll
            for (int q = 0; q < 4; q++) acc[mt][nt][q] = 0.f;

    #pragma unroll
    for (int ks = 0; ks < KSTEP; ks++) {
        int k0 = ks * 16 + tig * 2;
        unsigned a[2][4];
        #pragma unroll
        for (int mt = 0; mt < 2; mt++) {
            int g = m_base + mt * 16 + grp;
            a[mt][0] = *(const unsigned*)&sA[g * SAK + k0];
            a[mt][1] = *(const unsigned*)&sA[(g + 8) * SAK + k0];
            a[mt][2] = *(const unsigned*)&sA[g * SAK + k0 + 8];
            a[mt][3] = *(const unsigned*)&sA[(g + 8) * SAK + k0 + 8];
        }
        #pragma unroll
        for (int nt = 0; nt < NT_N; nt++) {
            int n = n_base + nt * 8 + grp;
            unsigned b0 = *(const unsigned*)&sB[n * SAK + k0];
            unsigned b1 = *(const unsigned*)&sB[n * SAK + k0 + 8];
            mma16816(acc[0][nt], a[0], b0, b1);
            mma16816(acc[1][nt], a[1], b0, b1);
        }
    }

    #pragma unroll
    for (int mt = 0; mt < 2; mt++) {
        int g0 = row0 + m_base + mt * 16 + grp;
        int g1 = g0 + 8;
        float ns0 = (g0 < Nn) ? g_norm_src[g0] : 0.f;
        float ns1 = (g1 < Nn) ? g_norm_src[g1] : 0.f;
        #pragma unroll
        for (int nt = 0; nt < NT_N; nt++) {
            int col = n_base + nt * 8 + tig * 2;
            if (g0 < Nn) {
                __half2 h = __floats2half2_rn(acc[mt][nt][0] * ns0, acc[mt][nt][1] * ns0);
                *(__half2*)&Cout[(size_t)g0 * DOUT + col] = h;
            }
            if (g1 < Nn) {
                __half2 h = __floats2half2_rn(acc[mt][nt][2] * ns1, acc[mt][nt][3] * ns1);
                *(__half2*)&Cout[(size_t)g1 * DOUT + col] = h;
            }
        }
    }
}

// ------- f32x2 SIMT GEMM (layers 3-5): fp16 A, fp32 W -------
template <int DIN, int DOUT>
__global__ void __launch_bounds__(256) gemm_kernel(const __half* __restrict__ A,
                                                   const float* __restrict__ W,
                                                   __half* __restrict__ Cout, int Nn) {
    constexpr int BM = 128;
    constexpr int BN = (DOUT < 64) ? DOUT : 64;
    constexpr int BK = 16;
    constexpr int TN = 4;
    constexpr int TXC = BN / TN;
    constexpr int TYC = 256 / TXC;
    constexpr int TM = BM / TYC;
    constexpr int TP = TM / 2;

    __shared__ float sA[BK][BM + 4];
    __shared__ float sB[BK][BN];

    int row0 = blockIdx.x * BM;
    int col0 = blockIdx.y * BN;
    int tx = threadIdx.x % TXC;
    int ty = threadIdx.x / TXC;

    u64 acc[TP][TN];
    #pragma unroll
    for (int p = 0; p < TP; p++)
        #pragma unroll
        for (int j = 0; j < TN; j++) acc[p][j] = 0ull;

    for (int k0 = 0; k0 < DIN; k0 += BK) {
        #pragma unroll
        for (int idx = threadIdx.x; idx < BM * BK / 4; idx += 256) {
            int r = idx / (BK / 4);
            int c4 = (idx % (BK / 4)) * 4;
            uint2 pk = *(const uint2*)&A[(size_t)(row0 + r) * DIN + k0 + c4];
            float2 v0 = __half22float2(*(__half2*)&pk.x);
            float2 v1 = __half22float2(*(__half2*)&pk.y);
            sA[c4 + 0][r] = v0.x; sA[c4 + 1][r] = v0.y;
            sA[c4 + 2][r] = v1.x; sA[c4 + 3][r] = v1.y;
        }
        #pragma unroll
        for (int idx = threadIdx.x; idx < BK * BN / 4; idx += 256) {
            int r = idx / (BN / 4);
            int c4 = (idx % (BN / 4)) * 4;
            *(float4*)&sB[r][c4] = *(const float4*)&W[(k0 + r) * DOUT + col0 + c4];
        }
        __syncthreads();
        #pragma unroll
        for (int kk = 0; kk < BK; kk++) {
            u64 a2[TP];
            #pragma unroll
            for (int p = 0; p < TP; p++)
                a2[p] = *(const u64*)&sA[kk][ty * TM + 2 * p];
            u64 b2[TN];
            #pragma unroll
            for (int j = 0; j < TN; j++)
                b2[j] = dup2(sB[kk][tx * TN + j]);
            #pragma unroll
            for (int p = 0; p < TP; p++)
                #pragma unroll
                for (int j = 0; j < TN; j++)
                    fma2(acc[p][j], a2[p], b2[j]);
        }
        __syncthreads();
    }
    #pragma unroll
    for (int p = 0; p < TP; p++) {
        float lo[TN], hi[TN];
        #pragma unroll
        for (int j = 0; j < TN; j++) unpack2(acc[p][j], lo[j], hi[j]);
        int gr = row0 + ty * TM + 2 * p;
        if (gr < Nn) {
            float ns = g_norm_src[gr];
            __half2 h0 = __floats2half2_rn(lo[0] * ns, lo[1] * ns);
            __half2 h1 = __floats2half2_rn(lo[2] * ns, lo[3] * ns);
            uint2 o; o.x = *(unsigned*)&h0; o.y = *(unsigned*)&h1;
            *(uint2*)&Cout[(size_t)gr * DOUT + col0 + tx * TN] = o;
        }
        if (gr + 1 < Nn) {
            float ns = g_norm_src[gr + 1];
            __half2 h0 = __floats2half2_rn(hi[0] * ns, hi[1] * ns);
            __half2 h1 = __floats2half2_rn(hi[2] * ns, hi[3] * ns);
            uint2 o; o.x = *(unsigned*)&h0; o.y = *(unsigned*)&h1;
            *(uint2*)&Cout[(size_t)(gr + 1) * DOUT + col0 + tx * TN] = o;
        }
    }
}

// ------- CSR gather (fp16 src) + norm_dst + bias + relu; fp16 or fp32 out -------
template <int D, bool HALF_OUT>
__global__ void __launch_bounds__(256) gather_kernel(const __half* __restrict__ t,
                                                     const float* __restrict__ bias,
                                                     void* __restrict__ outv, int Nn) {
    constexpr int TX = D / 4;
    int n = blockIdx.x * blockDim.y + threadIdx.y;
    if (n >= Nn) return;
    int f = threadIdx.x;
    const uint2* t4 = (const uint2*)t;
    int beg = g_rowptr[n], end = g_rowptr[n + 1];
    float4 acc = make_float4(0.f, 0.f, 0.f, 0.f);
    int j = beg;
    for (; j + 4 <= end; j += 4) {
        int s0 = g_esrc[j], s1 = g_esrc[j + 1], s2 = g_esrc[j + 2], s3 = g_esrc[j + 3];
        uint2 r0 = t4[s0 * TX + f];
        uint2 r1 = t4[s1 * TX + f];
        uint2 r2 = t4[s2 * TX + f];
        uint2 r3 = t4[s3 * TX + f];
        float2 a0 = __half22float2(*(__half2*)&r0.x), b0 = __half22float2(*(__half2*)&r0.y);
        float2 a1 = __half22float2(*(__half2*)&r1.x), b1 = __half22float2(*(__half2*)&r1.y);
        float2 a2 = __half22float2(*(__half2*)&r2.x), b2 = __half22float2(*(__half2*)&r2.y);
        float2 a3 = __half22float2(*(__half2*)&r3.x), b3 = __half22float2(*(__half2*)&r3.y);
        acc.x += (a0.x + a1.x) + (a2.x + a3.x);
        acc.y += (a0.y + a1.y) + (a2.y + a3.y);
        acc.z += (b0.x + b1.x) + (b2.x + b3.x);
        acc.w += (b0.y + b1.y) + (b2.y + b3.y);
    }
    for (; j < end; j++) {
        uint2 r = t4[g_esrc[j] * TX + f];
        float2 a = __half22float2(*(__half2*)&r.x), b = __half22float2(*(__half2*)&r.y);
        acc.x += a.x; acc.y += a.y; acc.z += b.x; acc.w += b.y;
    }
    float nd = g_norm_dst[n];
    float4 bb = ((const float4*)bias)[f];
    float4 o;
    o.x = fmaxf(fmaf(acc.x, nd, bb.x), 0.f);
    o.y = fmaxf(fmaf(acc.y, nd, bb.y), 0.f);
    o.z = fmaxf(fmaf(acc.z, nd, bb.z), 0.f);
    o.w = fmaxf(fmaf(acc.w, nd, bb.w), 0.f);
    if (HALF_OUT) {
        __half2 h0 = __floats2half2_rn(o.x, o.y);
        __half2 h1 = __floats2half2_rn(o.z, o.w);
        uint2 pk; pk.x = *(unsigned*)&h0; pk.y = *(unsigned*)&h1;
        ((uint2*)outv)[(size_t)n * TX + f] = pk;
    } else {
        ((float4*)outv)[(size_t)n * TX + f] = o;
    }
}

// ---------------- launch ----------------
extern "C" void kernel_launch(void* const* d_in, const int* in_sizes, int n_in,
                              void* d_out, int out_size) {
    const float* x  = (const float*)d_in[0];
    const int*   ed = (const int*)d_in[1];
    const float* W1 = (const float*)d_in[2];   const float* b1 = (const float*)d_in[3];
    const float* W2 = (const float*)d_in[4];   const float* b2 = (const float*)d_in[5];
    const float* W3 = (const float*)d_in[6];   const float* b3 = (const float*)d_in[7];
    const float* W4 = (const float*)d_in[8];   const float* b4 = (const float*)d_in[9];
    const float* W5 = (const float*)d_in[10];  const float* b5 = (const float*)d_in[11];

    const int Nn = in_sizes[0] / 128;
    const int E  = in_sizes[1] / 2;
    const int* src = ed;
    const int* dst = ed + E;

    // one-time side stream + events (host resources only; per-call GPU work unchanged)
    static cudaStream_t s1 = nullptr;
    static cudaEvent_t  eFork = nullptr, eScan = nullptr, eBin = nullptr;
    if (s1 == nullptr) {
        cudaStreamCreateWithFlags(&s1, cudaStreamNonBlocking);
        cudaEventCreateWithFlags(&eFork, cudaEventDisableTiming);
        cudaEventCreateWithFlags(&eScan, cudaEventDisableTiming);
        cudaEventCreateWithFlags(&eBin,  cudaEventDisableTiming);
    }

    void *pcs = nullptr, *pcd = nullptr, *pt = nullptr, *ph = nullptr, *px = nullptr;
    cudaGetSymbolAddress(&pcs, g_cnt_src);
    cudaGetSymbolAddress(&pcd, g_cnt_dst);
    cudaGetSymbolAddress(&pt,  g_t);
    cudaGetSymbolAddress(&ph,  g_h);
    cudaGetSymbolAddress(&px,  g_x16);
    __half* t   = (__half*)pt;
    __half* h   = (__half*)ph;
    __half* x16 = (__half*)px;

    // ---- stream 0: memsets, then fork prep chain onto s1 ----
    cudaMemsetAsync(pcs, 0, Nn * sizeof(int), 0);
    cudaMemsetAsync(pcd, 0, Nn * sizeof(int), 0);
    cudaEventRecord(eFork, 0);
    cudaStreamWaitEvent(s1, eFork, 0);

    int eb8 = (E / 8 + 255) / 256 + 1;
    int nsb = (Nn + SCB - 1) / SCB;
    degree_kernel<<<eb8, 256, 0, s1>>>(src, dst, E);
    scan_p1<<<nsb, 1024, 0, s1>>>(Nn);
    scan_p2<<<1, 32, 0, s1>>>(nsb);
    scan_p3<<<nsb, 1024, 0, s1>>>(Nn);
    cudaEventRecord(eScan, s1);
    bin_kernel<<<eb8, 256, 0, s1>>>(src, dst, E);
    cudaEventRecord(eBin, s1);

    // ---- stream 0: setup (x->fp16, W^T) overlaps prep chain ----
    int cvb = (Nn * 32 + 255) / 256;           // conversion blocks (float4 units)
    setup_kernel<<<cvb + 96, 256>>>(x, cvb, W1, W2);

    int mtiles = (Nn + 127) / 128;

    // Layer 1 GEMM needs norm_src (scan); overlaps with bin on s1
    cudaStreamWaitEvent(0, eScan, 0);
    const int SM1 = 256 * 272;
    cudaFuncSetAttribute(gemm_mma_kernel<128, 128, 0>,
                         cudaFuncAttributeMaxDynamicSharedMemorySize, SM1);
    gemm_mma_kernel<128, 128, 0><<<mtiles, 256, SM1>>>(x16, t, Nn);

    // gather1 additionally needs CSR (bin)
    cudaStreamWaitEvent(0, eBin, 0);
    gather_kernel<128, true><<<(Nn + 7) / 8, dim3(32, 8)>>>(t, b1, h, Nn);

    // Layer 2: 128 -> 64   (HMMA)
    const int SM2 = 192 * 272;
    cudaFuncSetAttribute(gemm_mma_kernel<128, 64, 17408>,
                         cudaFuncAttributeMaxDynamicSharedMemorySize, SM2);
    gemm_mma_kernel<128, 64, 17408><<<mtiles, 256, SM2>>>(h, t, Nn);
    gather_kernel<64, true><<<(Nn + 15) / 16, dim3(16, 16)>>>(t, b2, h, Nn);
    // Layer 3: 64 -> 32    (f32x2 SIMT)
    gemm_kernel<64, 32><<<dim3(mtiles, 1), 256>>>(h, W3, t, Nn);
    gather_kernel<32, true><<<(Nn + 31) / 32, dim3(8, 32)>>>(t, b3, h, Nn);
    // Layer 4: 32 -> 16
    gemm_kernel<32, 16><<<dim3(mtiles, 1), 256>>>(h, W4, t, Nn);
    gather_kernel<16, true><<<(Nn + 63) / 64, dim3(4, 64)>>>(t, b4, h, Nn);
    // Layer 5: 16 -> 16
    gemm_kernel<16, 16><<<dim3(mtiles, 1), 256>>>(h, W5, t, Nn);
    gather_kernel<16, false><<<(Nn + 63) / 64, dim3(4, 64)>>>(t, b5, d_out, Nn);
}